// round 9
// baseline (speedup 1.0000x reference)
#include <cuda_runtime.h>
#include <cuda_bf16.h>
#include <math.h>
#include <stdint.h>

#define B_TOK 8192
#define SEQ   64
#define EMB   512
#define NE    16
#define FFN   2048
#define CAP   512
#define NOUT  2
#define VOCAB 50000

// ------------------------- scratch (static device memory) -------------------
__device__ __nv_bfloat16  g_xm_bf[B_TOK * EMB];       // bf16 pooled embeddings (GEMM A)
__device__ __nv_bfloat16  g_embb[VOCAB * EMB];        // bf16 embedding table
__device__ float          g_gatev[B_TOK];             // gate prob of chosen expert
__device__ int            g_eidx[B_TOK];              // chosen expert per token
__device__ int            g_pos[B_TOK];               // slot within (chunk, expert)
__device__ int            g_ccnt[16 * NE];            // per-chunk expert counts
__device__ int            g_elist[NE * CAP];          // token id per (expert, slot), -1 empty
__device__ __nv_bfloat16  g_h[NE * CAP * FFN];        // hidden activations (post-relu)
__device__ float          g_logits[B_TOK * NOUT];     // pre-log-softmax logits (no fc_b)
__device__ int            g_done;                     // ffn2 completion counter (reset by last CTA)

// ------------------------------- helpers ------------------------------------
__device__ __forceinline__ unsigned su32(const void* p) {
    return (unsigned)__cvta_generic_to_shared(p);
}
__device__ __forceinline__ void ldsm4(unsigned addr, unsigned& r0, unsigned& r1,
                                      unsigned& r2, unsigned& r3) {
    asm volatile("ldmatrix.sync.aligned.m8n8.x4.shared.b16 {%0,%1,%2,%3}, [%4];"
                 : "=r"(r0), "=r"(r1), "=r"(r2), "=r"(r3) : "r"(addr));
}
__device__ __forceinline__ void ldsm4t(unsigned addr, unsigned& r0, unsigned& r1,
                                       unsigned& r2, unsigned& r3) {
    asm volatile("ldmatrix.sync.aligned.m8n8.x4.trans.shared.b16 {%0,%1,%2,%3}, [%4];"
                 : "=r"(r0), "=r"(r1), "=r"(r2), "=r"(r3) : "r"(addr));
}
__device__ __forceinline__ void mma16816(float* c, const unsigned* a, const unsigned* b) {
    asm volatile(
        "mma.sync.aligned.m16n8k16.row.col.f32.bf16.bf16.f32 "
        "{%0,%1,%2,%3}, {%4,%5,%6,%7}, {%8,%9}, {%0,%1,%2,%3};"
        : "+f"(c[0]), "+f"(c[1]), "+f"(c[2]), "+f"(c[3])
        : "r"(a[0]), "r"(a[1]), "r"(a[2]), "r"(a[3]), "r"(b[0]), "r"(b[1]));
}
__device__ __forceinline__ void cp16(unsigned dst, const void* src, bool pred) {
    int sz = pred ? 16 : 0;
    asm volatile("cp.async.cg.shared.global [%0], [%1], 16, %2;"
                 :: "r"(dst), "l"(src), "r"(sz));
}
#define CP_COMMIT asm volatile("cp.async.commit_group;")
#define CP_WAIT(n) asm volatile("cp.async.wait_group %0;" :: "n"(n))

// -------------------- 1) embedding fp32 -> bf16 convert ----------------------
__global__ __launch_bounds__(256) void k_cvt_emb(const float4* __restrict__ emb) {
    int i = blockIdx.x * 256 + threadIdx.x;   // VOCAB*EMB/8 threads
    float4 a = emb[2 * i];
    float4 b = emb[2 * i + 1];
    __nv_bfloat162* o = reinterpret_cast<__nv_bfloat162*>(g_embb);
    o[4 * i + 0] = __floats2bfloat162_rn(a.x, a.y);
    o[4 * i + 1] = __floats2bfloat162_rn(a.z, a.w);
    o[4 * i + 2] = __floats2bfloat162_rn(b.x, b.y);
    o[4 * i + 3] = __floats2bfloat162_rn(b.z, b.w);
}

// ---------- 2) fused: embedding gather + mean pool + gate (4 tokens/block) ----
#define WGP 520   // padded wg row pitch (floats)
__global__ __launch_bounds__(256) void k_pool_gate(const int* __restrict__ x,
                                                   const float* __restrict__ wg) {
    __shared__ float swg[NE * WGP];
    __shared__ float sxm[4][EMB];
    __shared__ int   toks[4][SEQ];
    __shared__ float glog[4][NE];

    int tid = threadIdx.x;
    for (int i = tid; i < EMB * NE; i += 256) {
        swg[(i & 15) * WGP + (i >> 4)] = wg[i];
    }
    toks[tid >> 6][tid & 63] = x[blockIdx.x * 256 + tid];
    __syncthreads();

    int grp = tid >> 6;
    int t   = tid & 63;
    int b   = blockIdx.x * 4 + grp;

    float acc[8];
#pragma unroll
    for (int j = 0; j < 8; j++) acc[j] = 0.f;

    const uint4* E = reinterpret_cast<const uint4*>(g_embb);
#pragma unroll 4
    for (int s = 0; s < SEQ; s += 4) {
        int i0 = toks[grp][s + 0] * (EMB / 8) + t;
        int i1 = toks[grp][s + 1] * (EMB / 8) + t;
        int i2 = toks[grp][s + 2] * (EMB / 8) + t;
        int i3 = toks[grp][s + 3] * (EMB / 8) + t;
        uint4 v0 = E[i0], v1 = E[i1], v2 = E[i2], v3 = E[i3];
        const __nv_bfloat162* p0 = reinterpret_cast<const __nv_bfloat162*>(&v0);
        const __nv_bfloat162* p1 = reinterpret_cast<const __nv_bfloat162*>(&v1);
        const __nv_bfloat162* p2 = reinterpret_cast<const __nv_bfloat162*>(&v2);
        const __nv_bfloat162* p3 = reinterpret_cast<const __nv_bfloat162*>(&v3);
#pragma unroll
        for (int j = 0; j < 4; j++) {
            __nv_bfloat162 a01 = __hadd2(p0[j], p1[j]);
            __nv_bfloat162 a23 = __hadd2(p2[j], p3[j]);
            __nv_bfloat162 q   = __hadd2(a01, a23);
            float2 f = __bfloat1622float2(q);
            acc[2 * j]     += f.x;
            acc[2 * j + 1] += f.y;
        }
    }
    const float inv = 1.0f / (float)SEQ;
#pragma unroll
    for (int j = 0; j < 8; j++) acc[j] *= inv;

    __nv_bfloat162 ob[4];
#pragma unroll
    for (int j = 0; j < 4; j++) ob[j] = __floats2bfloat162_rn(acc[2 * j], acc[2 * j + 1]);
    reinterpret_cast<uint4*>(g_xm_bf)[(size_t)b * (EMB / 8) + t] = *reinterpret_cast<uint4*>(ob);

    float4* sx = reinterpret_cast<float4*>(&sxm[grp][t * 8]);
    sx[0] = make_float4(acc[0], acc[1], acc[2], acc[3]);
    sx[1] = make_float4(acc[4], acc[5], acc[6], acc[7]);
    __syncthreads();

    int lane = tid & 31;
    int ebase = ((tid >> 5) & 1) * 8;
    float pe[8];
#pragma unroll
    for (int e = 0; e < 8; e++) pe[e] = 0.f;
#pragma unroll
    for (int j = 0; j < EMB / 32; j++) {
        int d = lane + 32 * j;
        float xv = sxm[grp][d];
#pragma unroll
        for (int e = 0; e < 8; e++) pe[e] += xv * swg[(ebase + e) * WGP + d];
    }
#pragma unroll
    for (int e = 0; e < 8; e++) {
#pragma unroll
        for (int o = 16; o > 0; o >>= 1) pe[e] += __shfl_xor_sync(0xffffffffu, pe[e], o);
    }
    if (lane == 0) {
#pragma unroll
        for (int e = 0; e < 8; e++) glog[grp][ebase + e] = pe[e];
    }
    __syncthreads();

    if (t == 0) {
        float z[NE];
#pragma unroll
        for (int e = 0; e < NE; e++) z[e] = glog[grp][e];
        float zm = z[0]; int idx = 0;
#pragma unroll
        for (int e = 1; e < NE; e++) {
            if (z[e] > zm) { zm = z[e]; idx = e; }
        }
        float s = 0.f;
#pragma unroll
        for (int e = 0; e < NE; e++) s += expf(z[e] - zm);
        g_eidx[b]  = idx;
        g_gatev[b] = 1.f / s;
        g_logits[2 * b]     = 0.f;
        g_logits[2 * b + 1] = 0.f;
    }
}

// -------------------- 3) parallel capacity routing (2 kernels) ----------------
__global__ __launch_bounds__(512) void k_route1() {
    __shared__ int wcnt[16][NE];
    int tid = threadIdx.x, c = blockIdx.x;
    int warp = tid >> 5, lane = tid & 31;

    for (int i = tid; i < NE * CAP / 16; i += 512) g_elist[c * (NE * CAP / 16) + i] = -1;
    if (tid < 16 * NE) ((int*)wcnt)[tid] = 0;
    __syncthreads();

    int b = c * 512 + tid;
    int e = g_eidx[b];
    unsigned m = __match_any_sync(0xffffffffu, e);
    int rank = __popc(m & ((1u << lane) - 1u));
    if (rank == 0) wcnt[warp][e] = __popc(m);
    __syncthreads();

    if (tid < NE) {
        int run = 0;
#pragma unroll
        for (int w = 0; w < 16; w++) {
            int v = wcnt[w][tid];
            wcnt[w][tid] = run;
            run += v;
        }
        g_ccnt[c * NE + tid] = run;
    }
    __syncthreads();
    g_pos[b] = wcnt[warp][e] + rank;
}

// scatter; per-block redundant scan of chunk bases (replaces old route2 kernel)
__global__ __launch_bounds__(512) void k_route3() {
    __shared__ int sbase[NE];
    int tid = threadIdx.x, c = blockIdx.x;
    if (tid < NE) {
        int run = 0;
        for (int cc = 0; cc < 16; cc++) {
            int v = g_ccnt[cc * NE + tid];
            if (cc == c) { sbase[tid] = run; }
            run += v;
        }
    }
    __syncthreads();
    int b = c * 512 + tid;
    int e = g_eidx[b];
    int pos = sbase[e] + g_pos[b];
    if (pos < CAP) g_elist[e * CAP + pos] = b;
}

// ------------- GEMM config (2-stage: A cp.async bf16, B LDG-fp32+cvt) --------
#define APITCH 40    // 32 + 8 bf16 pad
#define BPITCH 136   // 128 + 8 bf16 pad
#define ACH    (128 * APITCH * 2)          // 10240 B per A stage
#define BCH    (32 * BPITCH * 2)           // 8704 B per B stage
#define GHDR   2048                        // [0..512) sTok, [512..1536) sFc
#define SAOF   GHDR
#define SBOF   (GHDR + 2 * ACH)
#define GSMEM  (SBOF + 2 * BCH)            // 39936 B (< 48KB, no opt-in needed)

// -------------------- 4) FFN GEMM1: h = relu(xe @ w1 + b1) -------------------
__global__ __launch_bounds__(256) void k_ffn1(const float* __restrict__ w1,
                                              const float* __restrict__ b1) {
    extern __shared__ __align__(1024) char smem[];
    uint32_t sb = su32(smem);
    int* sTok = (int*)smem;

    int e  = blockIdx.z;
    int m0 = blockIdx.x * 128;
    int n0 = blockIdx.y * 128;
    int tid = threadIdx.x;

    if (tid < 128) sTok[tid] = g_elist[e * CAP + m0 + tid];
    __syncthreads();

    int ra0 = tid >> 2;
    int ka  = (tid & 3) * 8;
    int ra1 = ra0 + 64;
    int tok0 = sTok[ra0], tok1 = sTok[ra1];
    const __nv_bfloat16* A0 = g_xm_bf + (size_t)(tok0 < 0 ? 0 : tok0) * EMB + ka;
    const __nv_bfloat16* A1 = g_xm_bf + (size_t)(tok1 < 0 ? 0 : tok1) * EMB + ka;
    int rb0 = tid >> 4;
    int nb  = (tid & 15) * 8;
    const float* Bp = w1 + (size_t)e * EMB * FFN + (size_t)rb0 * FFN + n0 + nb;

    unsigned dA0[2], dA1[2];
    char* pB0[2]; char* pB1[2];
#pragma unroll
    for (int s = 0; s < 2; s++) {
        dA0[s] = sb + SAOF + s * ACH + (ra0 * APITCH + ka) * 2;
        dA1[s] = sb + SAOF + s * ACH + (ra1 * APITCH + ka) * 2;
        pB0[s] = smem + SBOF + s * BCH + (rb0 * BPITCH + nb) * 2;
        pB1[s] = smem + SBOF + s * BCH + ((rb0 + 16) * BPITCH + nb) * 2;
    }

    float breg[16];
    auto ldB = [&](int c) {
        const float* p = Bp + (size_t)(c * 32) * FFN;
        float4 x0 = *reinterpret_cast<const float4*>(p);
        float4 x1 = *reinterpret_cast<const float4*>(p + 4);
        float4 x2 = *reinterpret_cast<const float4*>(p + (size_t)16 * FFN);
        float4 x3 = *reinterpret_cast<const float4*>(p + (size_t)16 * FFN + 4);
        breg[0]=x0.x; breg[1]=x0.y; breg[2]=x0.z; breg[3]=x0.w;
        breg[4]=x1.x; breg[5]=x1.y; breg[6]=x1.z; breg[7]=x1.w;
        breg[8]=x2.x; breg[9]=x2.y; breg[10]=x2.z; breg[11]=x2.w;
        breg[12]=x3.x; breg[13]=x3.y; breg[14]=x3.z; breg[15]=x3.w;
    };
    auto stsB = [&](int s) {
        __nv_bfloat162 h0[4], h1[4];
#pragma unroll
        for (int q = 0; q < 4; q++) {
            h0[q] = __floats2bfloat162_rn(breg[2 * q],     breg[2 * q + 1]);
            h1[q] = __floats2bfloat162_rn(breg[8 + 2 * q], breg[8 + 2 * q + 1]);
        }
        *reinterpret_cast<uint4*>(pB0[s]) = *reinterpret_cast<uint4*>(h0);
        *reinterpret_cast<uint4*>(pB1[s]) = *reinterpret_cast<uint4*>(h1);
    };
    auto issueA = [&](int c, int s) {
        int k0 = c * 32;
        cp16(dA0[s], A0 + k0, tok0 >= 0);
        cp16(dA1[s], A1 + k0, tok1 >= 0);
        CP_COMMIT;
    };

    ldB(0);
    issueA(0, 0);

    int warp = tid >> 5;
    int wm = warp & 3, wn = warp >> 2;
    int lane = tid & 31;
    int g = lane >> 2, tq = lane & 3;
    int aRow = wm * 32 + (lane & 7) + ((lane >> 3) & 1) * 8;
    int aCol = (lane >> 4) * 8;
    int bRow = (lane & 7) + ((lane >> 3) & 1) * 8;
    int bCol = wn * 64 + (lane >> 4) * 8;

    float acc[2][8][4];
#pragma unroll
    for (int mi = 0; mi < 2; mi++)
#pragma unroll
        for (int ni = 0; ni < 8; ni++)
#pragma unroll
            for (int q = 0; q < 4; q++) acc[mi][ni][q] = 0.f;

    const int NK = EMB / 32;   // 16
#pragma unroll 1
    for (int ki = 0; ki < NK; ki++) {
        int s = ki & 1;
        stsB(s);
        if (ki + 1 < NK) { ldB(ki + 1); issueA(ki + 1, s ^ 1); CP_WAIT(1); }
        else             { CP_WAIT(0); }
        __syncthreads();
        unsigned aB = sb + SAOF + s * ACH;
        unsigned bB = sb + SBOF + s * BCH;
#pragma unroll
        for (int ks = 0; ks < 2; ks++) {
            unsigned a[2][4];
            ldsm4(aB + (unsigned)((aRow * APITCH + ks * 16 + aCol) * 2),
                  a[0][0], a[0][1], a[0][2], a[0][3]);
            ldsm4(aB + (unsigned)(((aRow + 16) * APITCH + ks * 16 + aCol) * 2),
                  a[1][0], a[1][1], a[1][2], a[1][3]);
            unsigned bf[8][2];
#pragma unroll
            for (int p = 0; p < 4; p++) {
                unsigned r0, r1, r2, r3;
                ldsm4t(bB + (unsigned)(((ks * 16 + bRow) * BPITCH + bCol + p * 16) * 2),
                       r0, r1, r2, r3);
                bf[2 * p][0] = r0; bf[2 * p][1] = r1;
                bf[2 * p + 1][0] = r2; bf[2 * p + 1][1] = r3;
            }
#pragma unroll
            for (int mi = 0; mi < 2; mi++)
#pragma unroll
                for (int ni = 0; ni < 8; ni++) mma16816(acc[mi][ni], a[mi], bf[ni]);
        }
        __syncthreads();
    }

    const float* b1e = b1 + e * FFN;
#pragma unroll
    for (int mi = 0; mi < 2; mi++) {
        int r0 = wm * 32 + mi * 16 + g;
#pragma unroll
        for (int ni = 0; ni < 8; ni++) {
            int nl = wn * 64 + ni * 8 + tq * 2;
            int n = n0 + nl;
            float bb0 = b1e[n], bb1 = b1e[n + 1];
            float h00 = fmaxf(acc[mi][ni][0] + bb0, 0.f);
            float h01 = fmaxf(acc[mi][ni][1] + bb1, 0.f);
            float h10 = fmaxf(acc[mi][ni][2] + bb0, 0.f);
            float h11 = fmaxf(acc[mi][ni][3] + bb1, 0.f);
            __nv_bfloat162* o0 = reinterpret_cast<__nv_bfloat162*>(
                g_h + (size_t)(e * CAP + m0 + r0) * FFN + n);
            __nv_bfloat162* o1 = reinterpret_cast<__nv_bfloat162*>(
                g_h + (size_t)(e * CAP + m0 + r0 + 8) * FFN + n);
            *o0 = __floats2bfloat162_rn(h00, h01);
            *o1 = __floats2bfloat162_rn(h10, h11);
        }
    }
}

// -- 5) FFN GEMM2 (split-K) + fused classifier + scatter + last-CTA log_softmax
#define FFN2_GRID (8 * (EMB / 128) * NE)    // 512 CTAs
__global__ __launch_bounds__(256) void k_ffn2(const float* __restrict__ w2,
                                              const float* __restrict__ b2,
                                              const float* __restrict__ fcw,
                                              const float* __restrict__ fcb,
                                              float* __restrict__ out) {
    extern __shared__ __align__(1024) char smem[];
    uint32_t sb = su32(smem);
    int*   sTok = (int*)smem;
    float* sFc  = (float*)(smem + 512);

    int e  = blockIdx.z;
    int kz = blockIdx.x >> 2;           // K-split half (0/1)
    int m0 = (blockIdx.x & 3) * 128;
    int n0 = blockIdx.y * 128;
    int kbase = kz * (FFN / 2);
    int tid = threadIdx.x;

    if (tid < 128) {
        sTok[tid] = g_elist[e * CAP + m0 + tid];
        sFc[2 * tid]     = fcw[(n0 + tid) * 2];
        sFc[2 * tid + 1] = fcw[(n0 + tid) * 2 + 1];
    }
    __syncthreads();

    int ra0 = tid >> 2;
    int ka  = (tid & 3) * 8;
    int ra1 = ra0 + 64;
    const __nv_bfloat16* Ab = g_h + (size_t)(e * CAP + m0) * FFN + kbase + ka;
    int rb0 = tid >> 4;
    int nb  = (tid & 15) * 8;
    const float* Bp = w2 + (size_t)e * FFN * EMB + (size_t)(kbase + rb0) * EMB + n0 + nb;

    unsigned dA0[2], dA1[2];
    char* pB0[2]; char* pB1[2];
#pragma unroll
    for (int s = 0; s < 2; s++) {
        dA0[s] = sb + SAOF + s * ACH + (ra0 * APITCH + ka) * 2;
        dA1[s] = sb + SAOF + s * ACH + (ra1 * APITCH + ka) * 2;
        pB0[s] = smem + SBOF + s * BCH + (rb0 * BPITCH + nb) * 2;
        pB1[s] = smem + SBOF + s * BCH + ((rb0 + 16) * BPITCH + nb) * 2;
    }

    float breg[16];
    auto ldB = [&](int c) {
        const float* p = Bp + (size_t)(c * 32) * EMB;
        float4 x0 = *reinterpret_cast<const float4*>(p);
        float4 x1 = *reinterpret_cast<const float4*>(p + 4);
        float4 x2 = *reinterpret_cast<const float4*>(p + (size_t)16 * EMB);
        float4 x3 = *reinterpret_cast<const float4*>(p + (size_t)16 * EMB + 4);
        breg[0]=x0.x; breg[1]=x0.y; breg[2]=x0.z; breg[3]=x0.w;
        breg[4]=x1.x; breg[5]=x1.y; breg[6]=x1.z; breg[7]=x1.w;
        breg[8]=x2.x; breg[9]=x2.y; breg[10]=x2.z; breg[11]=x2.w;
        breg[12]=x3.x; breg[13]=x3.y; breg[14]=x3.z; breg[15]=x3.w;
    };
    auto stsB = [&](int s) {
        __nv_bfloat162 h0[4], h1[4];
#pragma unroll
        for (int q = 0; q < 4; q++) {
            h0[q] = __floats2bfloat162_rn(breg[2 * q],     breg[2 * q + 1]);
            h1[q] = __floats2bfloat162_rn(breg[8 + 2 * q], breg[8 + 2 * q + 1]);
        }
        *reinterpret_cast<uint4*>(pB0[s]) = *reinterpret_cast<uint4*>(h0);
        *reinterpret_cast<uint4*>(pB1[s]) = *reinterpret_cast<uint4*>(h1);
    };
    auto issueA = [&](int c, int s) {
        int k0 = c * 32;
        cp16(dA0[s], Ab + (size_t)ra0 * FFN + k0, true);
        cp16(dA1[s], Ab + (size_t)ra1 * FFN + k0, true);
        CP_COMMIT;
    };

    ldB(0);
    issueA(0, 0);

    int warp = tid >> 5;
    int wm = warp & 3, wn = warp >> 2;
    int lane = tid & 31;
    int g = lane >> 2, tq = lane & 3;
    int aRow = wm * 32 + (lane & 7) + ((lane >> 3) & 1) * 8;
    int aCol = (lane >> 4) * 8;
    int bRow = (lane & 7) + ((lane >> 3) & 1) * 8;
    int bCol = wn * 64 + (lane >> 4) * 8;

    float acc[2][8][4];
#pragma unroll
    for (int mi = 0; mi < 2; mi++)
#pragma unroll
        for (int ni = 0; ni < 8; ni++)
#pragma unroll
            for (int q = 0; q < 4; q++) acc[mi][ni][q] = 0.f;

    const int NK = (FFN / 2) / 32;   // 32
#pragma unroll 1
    for (int ki = 0; ki < NK; ki++) {
        int s = ki & 1;
        stsB(s);
        if (ki + 1 < NK) { ldB(ki + 1); issueA(ki + 1, s ^ 1); CP_WAIT(1); }
        else             { CP_WAIT(0); }
        __syncthreads();
        unsigned aB = sb + SAOF + s * ACH;
        unsigned bB = sb + SBOF + s * BCH;
#pragma unroll
        for (int ks = 0; ks < 2; ks++) {
            unsigned a[2][4];
            ldsm4(aB + (unsigned)((aRow * APITCH + ks * 16 + aCol) * 2),
                  a[0][0], a[0][1], a[0][2], a[0][3]);
            ldsm4(aB + (unsigned)(((aRow + 16) * APITCH + ks * 16 + aCol) * 2),
                  a[1][0], a[1][1], a[1][2], a[1][3]);
            unsigned bf[8][2];
#pragma unroll
            for (int p = 0; p < 4; p++) {
                unsigned r0, r1, r2, r3;
                ldsm4t(bB + (unsigned)(((ks * 16 + bRow) * BPITCH + bCol + p * 16) * 2),
                       r0, r1, r2, r3);
                bf[2 * p][0] = r0; bf[2 * p][1] = r1;
                bf[2 * p + 1][0] = r2; bf[2 * p + 1][1] = r3;
            }
#pragma unroll
            for (int mi = 0; mi < 2; mi++)
#pragma unroll
                for (int ni = 0; ni < 8; ni++) mma16816(acc[mi][ni], a[mi], bf[ni]);
        }
        __syncthreads();
    }

    // epilogue: contract (acc + b2?) against fc_w columns, gate-scale, scatter
    float p[2][2][2];
#pragma unroll
    for (int mi = 0; mi < 2; mi++)
#pragma unroll
        for (int h = 0; h < 2; h++) { p[mi][h][0] = 0.f; p[mi][h][1] = 0.f; }

    const float* b2e = b2 + e * EMB;
    float bscale = (kz == 0) ? 1.f : 0.f;   // bias added by kz=0 half only
#pragma unroll
    for (int mi = 0; mi < 2; mi++) {
#pragma unroll
        for (int ni = 0; ni < 8; ni++) {
            int nl = wn * 64 + ni * 8 + tq * 2;
            float w00 = sFc[2 * nl],     w01 = sFc[2 * nl + 1];
            float w10 = sFc[2 * nl + 2], w11 = sFc[2 * nl + 3];
            float bb0 = bscale * b2e[n0 + nl], bb1 = bscale * b2e[n0 + nl + 1];
            float v0 = acc[mi][ni][0] + bb0, v1 = acc[mi][ni][1] + bb1;
            float v2 = acc[mi][ni][2] + bb0, v3 = acc[mi][ni][3] + bb1;
            p[mi][0][0] += v0 * w00 + v1 * w10;
            p[mi][0][1] += v0 * w01 + v1 * w11;
            p[mi][1][0] += v2 * w00 + v3 * w10;
            p[mi][1][1] += v2 * w01 + v3 * w11;
        }
    }
#pragma unroll
    for (int mi = 0; mi < 2; mi++) {
#pragma unroll
        for (int h = 0; h < 2; h++) {
            int row = wm * 32 + mi * 16 + g + h * 8;
            int tok = sTok[row];
            if (tok >= 0) {
                float gv = g_gatev[tok];
                atomicAdd(&g_logits[2 * tok],     gv * p[mi][h][0]);
                atomicAdd(&g_logits[2 * tok + 1], gv * p[mi][h][1]);
            }
        }
    }

    // ---- last-CTA: log_softmax over all tokens (replaces k_out launch) ----
    __shared__ int sIsLast;
    __threadfence();
    __syncthreads();
    if (tid == 0) {
        int old = atomicAdd(&g_done, 1);
        sIsLast = (old == FFN2_GRID - 1) ? 1 : 0;
    }
    __syncthreads();
    if (sIsLast) {
        float f0 = fcb[0], f1 = fcb[1];
        for (int b = tid; b < B_TOK; b += 256) {
            float z0 = g_logits[2 * b] + f0;
            float z1 = g_logits[2 * b + 1] + f1;
            float m = fmaxf(z0, z1);
            float l = m + logf(expf(z0 - m) + expf(z1 - m));
            out[2 * b]     = z0 - l;
            out[2 * b + 1] = z1 - l;
        }
        __syncthreads();
        if (tid == 0) g_done = 0;   // reset for next replay
    }
}

// ------------------------------- launcher ------------------------------------
extern "C" void kernel_launch(void* const* d_in, const int* in_sizes, int n_in,
                              void* d_out, int out_size) {
    (void)in_sizes; (void)n_in; (void)out_size;
    const int*   x   = (const int*)d_in[0];
    const float* emb = (const float*)d_in[1];
    const float* wg  = (const float*)d_in[2];
    const float* w1  = (const float*)d_in[3];
    const float* b1  = (const float*)d_in[4];
    const float* w2  = (const float*)d_in[5];
    const float* b2  = (const float*)d_in[6];
    const float* fcw = (const float*)d_in[7];
    const float* fcb = (const float*)d_in[8];
    float* out = (float*)d_out;

    k_cvt_emb<<<(VOCAB * EMB / 8) / 256, 256>>>((const float4*)emb);
    k_pool_gate<<<B_TOK / 4, 256>>>(x, wg);
    k_route1<<<16, 512>>>();
    k_route3<<<16, 512>>>();
    k_ffn1<<<dim3(CAP / 128, FFN / 128, NE), 256, GSMEM>>>(w1, b1);
    k_ffn2<<<dim3(8, EMB / 128, NE), 256, GSMEM>>>(w2, b2, fcw, fcb, out);
}

// round 10
// speedup vs baseline: 1.0613x; 1.0613x over previous
#include <cuda_runtime.h>
#include <cuda_bf16.h>
#include <math.h>
#include <stdint.h>

#define B_TOK 8192
#define SEQ   64
#define EMB   512
#define NE    16
#define FFN   2048
#define CAP   512
#define NOUT  2
#define VOCAB 50000

// ------------------------- scratch (static device memory) -------------------
__device__ __nv_bfloat16  g_xm_bf[B_TOK * EMB];       // bf16 pooled embeddings (GEMM A)
__device__ __nv_bfloat16  g_embb[VOCAB * EMB];        // bf16 embedding table
__device__ float          g_gatev[B_TOK];             // gate prob of chosen expert
__device__ int            g_eidx[B_TOK];              // chosen expert per token
__device__ int            g_pos[B_TOK];               // slot within (chunk, expert)
__device__ int            g_ccnt[16 * NE];            // per-chunk expert counts
__device__ int            g_elist[NE * CAP];          // token id per (expert, slot), -1 empty
__device__ __nv_bfloat16  g_h[NE * CAP * FFN];        // hidden activations (post-relu)
__device__ float          g_logits[B_TOK * NOUT];     // pre-log-softmax logits (no fc_b)

// ------------------------------- helpers ------------------------------------
__device__ __forceinline__ unsigned su32(const void* p) {
    return (unsigned)__cvta_generic_to_shared(p);
}
__device__ __forceinline__ void ldsm4(unsigned addr, unsigned& r0, unsigned& r1,
                                      unsigned& r2, unsigned& r3) {
    asm volatile("ldmatrix.sync.aligned.m8n8.x4.shared.b16 {%0,%1,%2,%3}, [%4];"
                 : "=r"(r0), "=r"(r1), "=r"(r2), "=r"(r3) : "r"(addr));
}
__device__ __forceinline__ void ldsm4t(unsigned addr, unsigned& r0, unsigned& r1,
                                       unsigned& r2, unsigned& r3) {
    asm volatile("ldmatrix.sync.aligned.m8n8.x4.trans.shared.b16 {%0,%1,%2,%3}, [%4];"
                 : "=r"(r0), "=r"(r1), "=r"(r2), "=r"(r3) : "r"(addr));
}
__device__ __forceinline__ void mma16816(float* c, const unsigned* a, const unsigned* b) {
    asm volatile(
        "mma.sync.aligned.m16n8k16.row.col.f32.bf16.bf16.f32 "
        "{%0,%1,%2,%3}, {%4,%5,%6,%7}, {%8,%9}, {%0,%1,%2,%3};"
        : "+f"(c[0]), "+f"(c[1]), "+f"(c[2]), "+f"(c[3])
        : "r"(a[0]), "r"(a[1]), "r"(a[2]), "r"(a[3]), "r"(b[0]), "r"(b[1]));
}
__device__ __forceinline__ void cp16(unsigned dst, const void* src, bool pred) {
    int sz = pred ? 16 : 0;
    asm volatile("cp.async.cg.shared.global [%0], [%1], 16, %2;"
                 :: "r"(dst), "l"(src), "r"(sz));
}
#define CP_COMMIT asm volatile("cp.async.commit_group;")
#define CP_WAIT(n) asm volatile("cp.async.wait_group %0;" :: "n"(n))

// -------------------- 1) embedding fp32 -> bf16 convert ----------------------
__global__ __launch_bounds__(256) void k_cvt_emb(const float4* __restrict__ emb) {
    int i = blockIdx.x * 256 + threadIdx.x;   // VOCAB*EMB/8 threads
    float4 a = emb[2 * i];
    float4 b = emb[2 * i + 1];
    __nv_bfloat162* o = reinterpret_cast<__nv_bfloat162*>(g_embb);
    o[4 * i + 0] = __floats2bfloat162_rn(a.x, a.y);
    o[4 * i + 1] = __floats2bfloat162_rn(a.z, a.w);
    o[4 * i + 2] = __floats2bfloat162_rn(b.x, b.y);
    o[4 * i + 3] = __floats2bfloat162_rn(b.z, b.w);
}

// ---------- 2) fused: embedding gather + mean pool + gate (4 tokens/block) ----
#define WGP 520   // padded wg row pitch (floats)
__global__ __launch_bounds__(256) void k_pool_gate(const int* __restrict__ x,
                                                   const float* __restrict__ wg) {
    __shared__ float swg[NE * WGP];
    __shared__ float sxm[4][EMB];
    __shared__ int   toks[4][SEQ];
    __shared__ float glog[4][NE];

    int tid = threadIdx.x;
    for (int i = tid; i < EMB * NE; i += 256) {
        swg[(i & 15) * WGP + (i >> 4)] = wg[i];
    }
    toks[tid >> 6][tid & 63] = x[blockIdx.x * 256 + tid];
    __syncthreads();

    int grp = tid >> 6;
    int t   = tid & 63;
    int b   = blockIdx.x * 4 + grp;

    float acc[8];
#pragma unroll
    for (int j = 0; j < 8; j++) acc[j] = 0.f;

    const uint4* E = reinterpret_cast<const uint4*>(g_embb);
#pragma unroll 4
    for (int s = 0; s < SEQ; s += 4) {
        int i0 = toks[grp][s + 0] * (EMB / 8) + t;
        int i1 = toks[grp][s + 1] * (EMB / 8) + t;
        int i2 = toks[grp][s + 2] * (EMB / 8) + t;
        int i3 = toks[grp][s + 3] * (EMB / 8) + t;
        uint4 v0 = E[i0], v1 = E[i1], v2 = E[i2], v3 = E[i3];
        const __nv_bfloat162* p0 = reinterpret_cast<const __nv_bfloat162*>(&v0);
        const __nv_bfloat162* p1 = reinterpret_cast<const __nv_bfloat162*>(&v1);
        const __nv_bfloat162* p2 = reinterpret_cast<const __nv_bfloat162*>(&v2);
        const __nv_bfloat162* p3 = reinterpret_cast<const __nv_bfloat162*>(&v3);
#pragma unroll
        for (int j = 0; j < 4; j++) {
            __nv_bfloat162 a01 = __hadd2(p0[j], p1[j]);
            __nv_bfloat162 a23 = __hadd2(p2[j], p3[j]);
            __nv_bfloat162 q   = __hadd2(a01, a23);
            float2 f = __bfloat1622float2(q);
            acc[2 * j]     += f.x;
            acc[2 * j + 1] += f.y;
        }
    }
    const float inv = 1.0f / (float)SEQ;
#pragma unroll
    for (int j = 0; j < 8; j++) acc[j] *= inv;

    __nv_bfloat162 ob[4];
#pragma unroll
    for (int j = 0; j < 4; j++) ob[j] = __floats2bfloat162_rn(acc[2 * j], acc[2 * j + 1]);
    reinterpret_cast<uint4*>(g_xm_bf)[(size_t)b * (EMB / 8) + t] = *reinterpret_cast<uint4*>(ob);

    float4* sx = reinterpret_cast<float4*>(&sxm[grp][t * 8]);
    sx[0] = make_float4(acc[0], acc[1], acc[2], acc[3]);
    sx[1] = make_float4(acc[4], acc[5], acc[6], acc[7]);
    __syncthreads();

    int lane = tid & 31;
    int ebase = ((tid >> 5) & 1) * 8;
    float pe[8];
#pragma unroll
    for (int e = 0; e < 8; e++) pe[e] = 0.f;
#pragma unroll
    for (int j = 0; j < EMB / 32; j++) {
        int d = lane + 32 * j;
        float xv = sxm[grp][d];
#pragma unroll
        for (int e = 0; e < 8; e++) pe[e] += xv * swg[(ebase + e) * WGP + d];
    }
#pragma unroll
    for (int e = 0; e < 8; e++) {
#pragma unroll
        for (int o = 16; o > 0; o >>= 1) pe[e] += __shfl_xor_sync(0xffffffffu, pe[e], o);
    }
    if (lane == 0) {
#pragma unroll
        for (int e = 0; e < 8; e++) glog[grp][ebase + e] = pe[e];
    }
    __syncthreads();

    if (t == 0) {
        float z[NE];
#pragma unroll
        for (int e = 0; e < NE; e++) z[e] = glog[grp][e];
        float zm = z[0]; int idx = 0;
#pragma unroll
        for (int e = 1; e < NE; e++) {
            if (z[e] > zm) { zm = z[e]; idx = e; }
        }
        float s = 0.f;
#pragma unroll
        for (int e = 0; e < NE; e++) s += expf(z[e] - zm);
        g_eidx[b]  = idx;
        g_gatev[b] = 1.f / s;
        g_logits[2 * b]     = 0.f;
        g_logits[2 * b + 1] = 0.f;
    }
}

// -------------------- 3) parallel capacity routing ----------------------------
__global__ __launch_bounds__(512) void k_route1() {
    __shared__ int wcnt[16][NE];
    int tid = threadIdx.x, c = blockIdx.x;
    int warp = tid >> 5, lane = tid & 31;

    for (int i = tid; i < NE * CAP / 16; i += 512) g_elist[c * (NE * CAP / 16) + i] = -1;
    if (tid < 16 * NE) ((int*)wcnt)[tid] = 0;
    __syncthreads();

    int b = c * 512 + tid;
    int e = g_eidx[b];
    unsigned m = __match_any_sync(0xffffffffu, e);
    int rank = __popc(m & ((1u << lane) - 1u));
    if (rank == 0) wcnt[warp][e] = __popc(m);
    __syncthreads();

    if (tid < NE) {
        int run = 0;
#pragma unroll
        for (int w = 0; w < 16; w++) {
            int v = wcnt[w][tid];
            wcnt[w][tid] = run;
            run += v;
        }
        g_ccnt[c * NE + tid] = run;
    }
    __syncthreads();
    g_pos[b] = wcnt[warp][e] + rank;
}

// scatter; per-block redundant scan of chunk bases (replaces old route2 kernel)
__global__ __launch_bounds__(512) void k_route3() {
    __shared__ int sbase[NE];
    int tid = threadIdx.x, c = blockIdx.x;
    if (tid < NE) {
        int run = 0;
        for (int cc = 0; cc < 16; cc++) {
            int v = g_ccnt[cc * NE + tid];
            if (cc == c) { sbase[tid] = run; }
            run += v;
        }
    }
    __syncthreads();
    int b = c * 512 + tid;
    int e = g_eidx[b];
    int pos = sbase[e] + g_pos[b];
    if (pos < CAP) g_elist[e * CAP + pos] = b;
}

// ------------- GEMM config (2-stage: A cp.async bf16, B LDG-fp32+cvt) --------
#define APITCH 40    // 32 + 8 bf16 pad
#define BPITCH 136   // 128 + 8 bf16 pad
#define ACH    (128 * APITCH * 2)          // 10240 B per A stage
#define BCH    (32 * BPITCH * 2)           // 8704 B per B stage
#define GHDR   2048                        // [0..512) sTok, [512..1536) sFc
#define SAOF   GHDR
#define SBOF   (GHDR + 2 * ACH)
#define GSMEM  (SBOF + 2 * BCH)            // 39936 B (< 48KB, no opt-in needed)

// -------------------- 4) FFN GEMM1: h = relu(xe @ w1 + b1) -------------------
__global__ __launch_bounds__(256) void k_ffn1(const float* __restrict__ w1,
                                              const float* __restrict__ b1) {
    extern __shared__ __align__(1024) char smem[];
    uint32_t sb = su32(smem);
    int* sTok = (int*)smem;

    int e  = blockIdx.z;
    int m0 = blockIdx.x * 128;
    int n0 = blockIdx.y * 128;
    int tid = threadIdx.x;

    if (tid < 128) sTok[tid] = g_elist[e * CAP + m0 + tid];
    __syncthreads();

    int ra0 = tid >> 2;
    int ka  = (tid & 3) * 8;
    int ra1 = ra0 + 64;
    int tok0 = sTok[ra0], tok1 = sTok[ra1];
    const __nv_bfloat16* A0 = g_xm_bf + (size_t)(tok0 < 0 ? 0 : tok0) * EMB + ka;
    const __nv_bfloat16* A1 = g_xm_bf + (size_t)(tok1 < 0 ? 0 : tok1) * EMB + ka;
    int rb0 = tid >> 4;
    int nb  = (tid & 15) * 8;
    const float* Bp = w1 + (size_t)e * EMB * FFN + (size_t)rb0 * FFN + n0 + nb;

    unsigned dA0[2], dA1[2];
    char* pB0[2]; char* pB1[2];
#pragma unroll
    for (int s = 0; s < 2; s++) {
        dA0[s] = sb + SAOF + s * ACH + (ra0 * APITCH + ka) * 2;
        dA1[s] = sb + SAOF + s * ACH + (ra1 * APITCH + ka) * 2;
        pB0[s] = smem + SBOF + s * BCH + (rb0 * BPITCH + nb) * 2;
        pB1[s] = smem + SBOF + s * BCH + ((rb0 + 16) * BPITCH + nb) * 2;
    }

    float breg[16];
    auto ldB = [&](int c) {
        const float* p = Bp + (size_t)(c * 32) * FFN;
        float4 x0 = *reinterpret_cast<const float4*>(p);
        float4 x1 = *reinterpret_cast<const float4*>(p + 4);
        float4 x2 = *reinterpret_cast<const float4*>(p + (size_t)16 * FFN);
        float4 x3 = *reinterpret_cast<const float4*>(p + (size_t)16 * FFN + 4);
        breg[0]=x0.x; breg[1]=x0.y; breg[2]=x0.z; breg[3]=x0.w;
        breg[4]=x1.x; breg[5]=x1.y; breg[6]=x1.z; breg[7]=x1.w;
        breg[8]=x2.x; breg[9]=x2.y; breg[10]=x2.z; breg[11]=x2.w;
        breg[12]=x3.x; breg[13]=x3.y; breg[14]=x3.z; breg[15]=x3.w;
    };
    auto stsB = [&](int s) {
        __nv_bfloat162 h0[4], h1[4];
#pragma unroll
        for (int q = 0; q < 4; q++) {
            h0[q] = __floats2bfloat162_rn(breg[2 * q],     breg[2 * q + 1]);
            h1[q] = __floats2bfloat162_rn(breg[8 + 2 * q], breg[8 + 2 * q + 1]);
        }
        *reinterpret_cast<uint4*>(pB0[s]) = *reinterpret_cast<uint4*>(h0);
        *reinterpret_cast<uint4*>(pB1[s]) = *reinterpret_cast<uint4*>(h1);
    };
    auto issueA = [&](int c, int s) {
        int k0 = c * 32;
        cp16(dA0[s], A0 + k0, tok0 >= 0);
        cp16(dA1[s], A1 + k0, tok1 >= 0);
        CP_COMMIT;
    };

    ldB(0);
    issueA(0, 0);

    int warp = tid >> 5;
    int wm = warp & 3, wn = warp >> 2;
    int lane = tid & 31;
    int g = lane >> 2, tq = lane & 3;
    int aRow = wm * 32 + (lane & 7) + ((lane >> 3) & 1) * 8;
    int aCol = (lane >> 4) * 8;
    int bRow = (lane & 7) + ((lane >> 3) & 1) * 8;
    int bCol = wn * 64 + (lane >> 4) * 8;

    float acc[2][8][4];
#pragma unroll
    for (int mi = 0; mi < 2; mi++)
#pragma unroll
        for (int ni = 0; ni < 8; ni++)
#pragma unroll
            for (int q = 0; q < 4; q++) acc[mi][ni][q] = 0.f;

    const int NK = EMB / 32;   // 16
#pragma unroll 1
    for (int ki = 0; ki < NK; ki++) {
        int s = ki & 1;
        stsB(s);
        if (ki + 1 < NK) { ldB(ki + 1); issueA(ki + 1, s ^ 1); CP_WAIT(1); }
        else             { CP_WAIT(0); }
        __syncthreads();
        unsigned aB = sb + SAOF + s * ACH;
        unsigned bB = sb + SBOF + s * BCH;
#pragma unroll
        for (int ks = 0; ks < 2; ks++) {
            unsigned a[2][4];
            ldsm4(aB + (unsigned)((aRow * APITCH + ks * 16 + aCol) * 2),
                  a[0][0], a[0][1], a[0][2], a[0][3]);
            ldsm4(aB + (unsigned)(((aRow + 16) * APITCH + ks * 16 + aCol) * 2),
                  a[1][0], a[1][1], a[1][2], a[1][3]);
            unsigned bf[8][2];
#pragma unroll
            for (int p = 0; p < 4; p++) {
                unsigned r0, r1, r2, r3;
                ldsm4t(bB + (unsigned)(((ks * 16 + bRow) * BPITCH + bCol + p * 16) * 2),
                       r0, r1, r2, r3);
                bf[2 * p][0] = r0; bf[2 * p][1] = r1;
                bf[2 * p + 1][0] = r2; bf[2 * p + 1][1] = r3;
            }
#pragma unroll
            for (int mi = 0; mi < 2; mi++)
#pragma unroll
                for (int ni = 0; ni < 8; ni++) mma16816(acc[mi][ni], a[mi], bf[ni]);
        }
        __syncthreads();
    }

    const float* b1e = b1 + e * FFN;
#pragma unroll
    for (int mi = 0; mi < 2; mi++) {
        int r0 = wm * 32 + mi * 16 + g;
#pragma unroll
        for (int ni = 0; ni < 8; ni++) {
            int nl = wn * 64 + ni * 8 + tq * 2;
            int n = n0 + nl;
            float bb0 = b1e[n], bb1 = b1e[n + 1];
            float h00 = fmaxf(acc[mi][ni][0] + bb0, 0.f);
            float h01 = fmaxf(acc[mi][ni][1] + bb1, 0.f);
            float h10 = fmaxf(acc[mi][ni][2] + bb0, 0.f);
            float h11 = fmaxf(acc[mi][ni][3] + bb1, 0.f);
            __nv_bfloat162* o0 = reinterpret_cast<__nv_bfloat162*>(
                g_h + (size_t)(e * CAP + m0 + r0) * FFN + n);
            __nv_bfloat162* o1 = reinterpret_cast<__nv_bfloat162*>(
                g_h + (size_t)(e * CAP + m0 + r0 + 8) * FFN + n);
            *o0 = __floats2bfloat162_rn(h00, h01);
            *o1 = __floats2bfloat162_rn(h10, h11);
        }
    }
}

// ---- 5) FFN GEMM2 (split-K): ye = h @ w2 + b2, fused classifier + scatter ---
__global__ __launch_bounds__(256) void k_ffn2(const float* __restrict__ w2,
                                              const float* __restrict__ b2,
                                              const float* __restrict__ fcw) {
    extern __shared__ __align__(1024) char smem[];
    uint32_t sb = su32(smem);
    int*   sTok = (int*)smem;
    float* sFc  = (float*)(smem + 512);

    int e  = blockIdx.z;
    int kz = blockIdx.x >> 2;           // K-split half (0/1)
    int m0 = (blockIdx.x & 3) * 128;
    int n0 = blockIdx.y * 128;
    int kbase = kz * (FFN / 2);
    int tid = threadIdx.x;

    if (tid < 128) {
        sTok[tid] = g_elist[e * CAP + m0 + tid];
        sFc[2 * tid]     = fcw[(n0 + tid) * 2];
        sFc[2 * tid + 1] = fcw[(n0 + tid) * 2 + 1];
    }
    __syncthreads();

    int ra0 = tid >> 2;
    int ka  = (tid & 3) * 8;
    int ra1 = ra0 + 64;
    const __nv_bfloat16* Ab = g_h + (size_t)(e * CAP + m0) * FFN + kbase + ka;
    int rb0 = tid >> 4;
    int nb  = (tid & 15) * 8;
    const float* Bp = w2 + (size_t)e * FFN * EMB + (size_t)(kbase + rb0) * EMB + n0 + nb;

    unsigned dA0[2], dA1[2];
    char* pB0[2]; char* pB1[2];
#pragma unroll
    for (int s = 0; s < 2; s++) {
        dA0[s] = sb + SAOF + s * ACH + (ra0 * APITCH + ka) * 2;
        dA1[s] = sb + SAOF + s * ACH + (ra1 * APITCH + ka) * 2;
        pB0[s] = smem + SBOF + s * BCH + (rb0 * BPITCH + nb) * 2;
        pB1[s] = smem + SBOF + s * BCH + ((rb0 + 16) * BPITCH + nb) * 2;
    }

    float breg[16];
    auto ldB = [&](int c) {
        const float* p = Bp + (size_t)(c * 32) * EMB;
        float4 x0 = *reinterpret_cast<const float4*>(p);
        float4 x1 = *reinterpret_cast<const float4*>(p + 4);
        float4 x2 = *reinterpret_cast<const float4*>(p + (size_t)16 * EMB);
        float4 x3 = *reinterpret_cast<const float4*>(p + (size_t)16 * EMB + 4);
        breg[0]=x0.x; breg[1]=x0.y; breg[2]=x0.z; breg[3]=x0.w;
        breg[4]=x1.x; breg[5]=x1.y; breg[6]=x1.z; breg[7]=x1.w;
        breg[8]=x2.x; breg[9]=x2.y; breg[10]=x2.z; breg[11]=x2.w;
        breg[12]=x3.x; breg[13]=x3.y; breg[14]=x3.z; breg[15]=x3.w;
    };
    auto stsB = [&](int s) {
        __nv_bfloat162 h0[4], h1[4];
#pragma unroll
        for (int q = 0; q < 4; q++) {
            h0[q] = __floats2bfloat162_rn(breg[2 * q],     breg[2 * q + 1]);
            h1[q] = __floats2bfloat162_rn(breg[8 + 2 * q], breg[8 + 2 * q + 1]);
        }
        *reinterpret_cast<uint4*>(pB0[s]) = *reinterpret_cast<uint4*>(h0);
        *reinterpret_cast<uint4*>(pB1[s]) = *reinterpret_cast<uint4*>(h1);
    };
    auto issueA = [&](int c, int s) {
        int k0 = c * 32;
        cp16(dA0[s], Ab + (size_t)ra0 * FFN + k0, true);
        cp16(dA1[s], Ab + (size_t)ra1 * FFN + k0, true);
        CP_COMMIT;
    };

    ldB(0);
    issueA(0, 0);

    int warp = tid >> 5;
    int wm = warp & 3, wn = warp >> 2;
    int lane = tid & 31;
    int g = lane >> 2, tq = lane & 3;
    int aRow = wm * 32 + (lane & 7) + ((lane >> 3) & 1) * 8;
    int aCol = (lane >> 4) * 8;
    int bRow = (lane & 7) + ((lane >> 3) & 1) * 8;
    int bCol = wn * 64 + (lane >> 4) * 8;

    float acc[2][8][4];
#pragma unroll
    for (int mi = 0; mi < 2; mi++)
#pragma unroll
        for (int ni = 0; ni < 8; ni++)
#pragma unroll
            for (int q = 0; q < 4; q++) acc[mi][ni][q] = 0.f;

    const int NK = (FFN / 2) / 32;   // 32
#pragma unroll 1
    for (int ki = 0; ki < NK; ki++) {
        int s = ki & 1;
        stsB(s);
        if (ki + 1 < NK) { ldB(ki + 1); issueA(ki + 1, s ^ 1); CP_WAIT(1); }
        else             { CP_WAIT(0); }
        __syncthreads();
        unsigned aB = sb + SAOF + s * ACH;
        unsigned bB = sb + SBOF + s * BCH;
#pragma unroll
        for (int ks = 0; ks < 2; ks++) {
            unsigned a[2][4];
            ldsm4(aB + (unsigned)((aRow * APITCH + ks * 16 + aCol) * 2),
                  a[0][0], a[0][1], a[0][2], a[0][3]);
            ldsm4(aB + (unsigned)(((aRow + 16) * APITCH + ks * 16 + aCol) * 2),
                  a[1][0], a[1][1], a[1][2], a[1][3]);
            unsigned bf[8][2];
#pragma unroll
            for (int p = 0; p < 4; p++) {
                unsigned r0, r1, r2, r3;
                ldsm4t(bB + (unsigned)(((ks * 16 + bRow) * BPITCH + bCol + p * 16) * 2),
                       r0, r1, r2, r3);
                bf[2 * p][0] = r0; bf[2 * p][1] = r1;
                bf[2 * p + 1][0] = r2; bf[2 * p + 1][1] = r3;
            }
#pragma unroll
            for (int mi = 0; mi < 2; mi++)
#pragma unroll
                for (int ni = 0; ni < 8; ni++) mma16816(acc[mi][ni], a[mi], bf[ni]);
        }
        __syncthreads();
    }

    // epilogue: contract (acc + b2?) against fc_w columns, gate-scale, scatter
    float p[2][2][2];
#pragma unroll
    for (int mi = 0; mi < 2; mi++)
#pragma unroll
        for (int h = 0; h < 2; h++) { p[mi][h][0] = 0.f; p[mi][h][1] = 0.f; }

    const float* b2e = b2 + e * EMB;
    float bscale = (kz == 0) ? 1.f : 0.f;   // bias added by kz=0 half only
#pragma unroll
    for (int mi = 0; mi < 2; mi++) {
#pragma unroll
        for (int ni = 0; ni < 8; ni++) {
            int nl = wn * 64 + ni * 8 + tq * 2;
            float w00 = sFc[2 * nl],     w01 = sFc[2 * nl + 1];
            float w10 = sFc[2 * nl + 2], w11 = sFc[2 * nl + 3];
            float bb0 = bscale * b2e[n0 + nl], bb1 = bscale * b2e[n0 + nl + 1];
            float v0 = acc[mi][ni][0] + bb0, v1 = acc[mi][ni][1] + bb1;
            float v2 = acc[mi][ni][2] + bb0, v3 = acc[mi][ni][3] + bb1;
            p[mi][0][0] += v0 * w00 + v1 * w10;
            p[mi][0][1] += v0 * w01 + v1 * w11;
            p[mi][1][0] += v2 * w00 + v3 * w10;
            p[mi][1][1] += v2 * w01 + v3 * w11;
        }
    }
#pragma unroll
    for (int mi = 0; mi < 2; mi++) {
#pragma unroll
        for (int h = 0; h < 2; h++) {
            int row = wm * 32 + mi * 16 + g + h * 8;
            int tok = sTok[row];
            if (tok >= 0) {
                float gv = g_gatev[tok];
                atomicAdd(&g_logits[2 * tok],     gv * p[mi][h][0]);
                atomicAdd(&g_logits[2 * tok + 1], gv * p[mi][h][1]);
            }
        }
    }
}

// -------------------- 6) final log_softmax -----------------------------------
__global__ void k_out(const float* __restrict__ fcb, float* __restrict__ out) {
    int b = blockIdx.x * blockDim.x + threadIdx.x;
    if (b < B_TOK) {
        float z0 = g_logits[2 * b] + fcb[0];
        float z1 = g_logits[2 * b + 1] + fcb[1];
        float m = fmaxf(z0, z1);
        float l = m + logf(expf(z0 - m) + expf(z1 - m));
        out[2 * b]     = z0 - l;
        out[2 * b + 1] = z1 - l;
    }
}

// ------------------------------- launcher ------------------------------------
extern "C" void kernel_launch(void* const* d_in, const int* in_sizes, int n_in,
                              void* d_out, int out_size) {
    (void)in_sizes; (void)n_in; (void)out_size;
    const int*   x   = (const int*)d_in[0];
    const float* emb = (const float*)d_in[1];
    const float* wg  = (const float*)d_in[2];
    const float* w1  = (const float*)d_in[3];
    const float* b1  = (const float*)d_in[4];
    const float* w2  = (const float*)d_in[5];
    const float* b2  = (const float*)d_in[6];
    const float* fcw = (const float*)d_in[7];
    const float* fcb = (const float*)d_in[8];
    float* out = (float*)d_out;

    k_cvt_emb<<<(VOCAB * EMB / 8) / 256, 256>>>((const float4*)emb);
    k_pool_gate<<<B_TOK / 4, 256>>>(x, wg);
    k_route1<<<16, 512>>>();
    k_route3<<<16, 512>>>();
    k_ffn1<<<dim3(CAP / 128, FFN / 128, NE), 256, GSMEM>>>(w1, b1);
    k_ffn2<<<dim3(8, EMB / 128, NE), 256, GSMEM>>>(w2, b2, fcw);
    k_out<<<B_TOK / 256, 256>>>(fcb, out);
}

// round 11
// speedup vs baseline: 1.0976x; 1.0342x over previous
#include <cuda_runtime.h>
#include <cuda_bf16.h>
#include <math.h>
#include <stdint.h>

#define B_TOK 8192
#define SEQ   64
#define EMB   512
#define NE    16
#define FFN   2048
#define CAP   512
#define NOUT  2
#define VOCAB 50000

// ------------------------- scratch (static device memory) -------------------
__device__ __nv_bfloat16  g_xm_bf[B_TOK * EMB];       // bf16 pooled embeddings (GEMM A)
__device__ __nv_bfloat16  g_embb[VOCAB * EMB];        // bf16 embedding table
__device__ float          g_gatev[B_TOK];             // gate prob of chosen expert
__device__ int            g_eidx[B_TOK];              // chosen expert per token
__device__ int            g_pos[B_TOK];               // slot within (chunk, expert)
__device__ int            g_ccnt[16 * NE];            // per-chunk expert counts
__device__ int            g_elist[NE * CAP];          // token id per (expert, slot), -1 empty
__device__ __nv_bfloat16  g_h[NE * CAP * FFN];        // hidden activations (post-relu)
__device__ float          g_logits[B_TOK * NOUT];     // pre-log-softmax logits (no fc_b)

// ------------------------------- helpers ------------------------------------
__device__ __forceinline__ unsigned su32(const void* p) {
    return (unsigned)__cvta_generic_to_shared(p);
}
__device__ __forceinline__ void ldsm4(unsigned addr, unsigned& r0, unsigned& r1,
                                      unsigned& r2, unsigned& r3) {
    asm volatile("ldmatrix.sync.aligned.m8n8.x4.shared.b16 {%0,%1,%2,%3}, [%4];"
                 : "=r"(r0), "=r"(r1), "=r"(r2), "=r"(r3) : "r"(addr));
}
__device__ __forceinline__ void ldsm4t(unsigned addr, unsigned& r0, unsigned& r1,
                                       unsigned& r2, unsigned& r3) {
    asm volatile("ldmatrix.sync.aligned.m8n8.x4.trans.shared.b16 {%0,%1,%2,%3}, [%4];"
                 : "=r"(r0), "=r"(r1), "=r"(r2), "=r"(r3) : "r"(addr));
}
__device__ __forceinline__ void mma16816(float* c, const unsigned* a, const unsigned* b) {
    asm volatile(
        "mma.sync.aligned.m16n8k16.row.col.f32.bf16.bf16.f32 "
        "{%0,%1,%2,%3}, {%4,%5,%6,%7}, {%8,%9}, {%0,%1,%2,%3};"
        : "+f"(c[0]), "+f"(c[1]), "+f"(c[2]), "+f"(c[3])
        : "r"(a[0]), "r"(a[1]), "r"(a[2]), "r"(a[3]), "r"(b[0]), "r"(b[1]));
}
__device__ __forceinline__ void cp16(unsigned dst, const void* src, bool pred) {
    int sz = pred ? 16 : 0;
    asm volatile("cp.async.cg.shared.global [%0], [%1], 16, %2;"
                 :: "r"(dst), "l"(src), "r"(sz));
}
#define CP_COMMIT asm volatile("cp.async.commit_group;")
#define CP_WAIT(n) asm volatile("cp.async.wait_group %0;" :: "n"(n))

// -------------------- 1) embedding fp32 -> bf16 convert ----------------------
__global__ __launch_bounds__(256) void k_cvt_emb(const float4* __restrict__ emb) {
    int i = blockIdx.x * 256 + threadIdx.x;   // VOCAB*EMB/8 threads
    float4 a = emb[2 * i];
    float4 b = emb[2 * i + 1];
    __nv_bfloat162* o = reinterpret_cast<__nv_bfloat162*>(g_embb);
    o[4 * i + 0] = __floats2bfloat162_rn(a.x, a.y);
    o[4 * i + 1] = __floats2bfloat162_rn(a.z, a.w);
    o[4 * i + 2] = __floats2bfloat162_rn(b.x, b.y);
    o[4 * i + 3] = __floats2bfloat162_rn(b.z, b.w);
}

// ---------- 2) fused: embedding gather + mean pool + gate (4 tokens/block) ----
#define WGP 520   // padded wg row pitch (floats)
__global__ __launch_bounds__(256) void k_pool_gate(const int* __restrict__ x,
                                                   const float* __restrict__ wg) {
    __shared__ float swg[NE * WGP];
    __shared__ float sxm[4][EMB];
    __shared__ int   toks[4][SEQ];
    __shared__ float glog[4][NE];

    int tid = threadIdx.x;
    for (int i = tid; i < EMB * NE; i += 256) {
        swg[(i & 15) * WGP + (i >> 4)] = wg[i];
    }
    toks[tid >> 6][tid & 63] = x[blockIdx.x * 256 + tid];
    __syncthreads();

    int grp = tid >> 6;
    int t   = tid & 63;
    int b   = blockIdx.x * 4 + grp;

    float acc[8];
#pragma unroll
    for (int j = 0; j < 8; j++) acc[j] = 0.f;

    const uint4* E = reinterpret_cast<const uint4*>(g_embb);
#pragma unroll 4
    for (int s = 0; s < SEQ; s += 4) {
        int i0 = toks[grp][s + 0] * (EMB / 8) + t;
        int i1 = toks[grp][s + 1] * (EMB / 8) + t;
        int i2 = toks[grp][s + 2] * (EMB / 8) + t;
        int i3 = toks[grp][s + 3] * (EMB / 8) + t;
        uint4 v0 = E[i0], v1 = E[i1], v2 = E[i2], v3 = E[i3];
        const __nv_bfloat162* p0 = reinterpret_cast<const __nv_bfloat162*>(&v0);
        const __nv_bfloat162* p1 = reinterpret_cast<const __nv_bfloat162*>(&v1);
        const __nv_bfloat162* p2 = reinterpret_cast<const __nv_bfloat162*>(&v2);
        const __nv_bfloat162* p3 = reinterpret_cast<const __nv_bfloat162*>(&v3);
#pragma unroll
        for (int j = 0; j < 4; j++) {
            __nv_bfloat162 a01 = __hadd2(p0[j], p1[j]);
            __nv_bfloat162 a23 = __hadd2(p2[j], p3[j]);
            __nv_bfloat162 q   = __hadd2(a01, a23);
            float2 f = __bfloat1622float2(q);
            acc[2 * j]     += f.x;
            acc[2 * j + 1] += f.y;
        }
    }
    const float inv = 1.0f / (float)SEQ;
#pragma unroll
    for (int j = 0; j < 8; j++) acc[j] *= inv;

    __nv_bfloat162 ob[4];
#pragma unroll
    for (int j = 0; j < 4; j++) ob[j] = __floats2bfloat162_rn(acc[2 * j], acc[2 * j + 1]);
    reinterpret_cast<uint4*>(g_xm_bf)[(size_t)b * (EMB / 8) + t] = *reinterpret_cast<uint4*>(ob);

    float4* sx = reinterpret_cast<float4*>(&sxm[grp][t * 8]);
    sx[0] = make_float4(acc[0], acc[1], acc[2], acc[3]);
    sx[1] = make_float4(acc[4], acc[5], acc[6], acc[7]);
    __syncthreads();

    int lane = tid & 31;
    int ebase = ((tid >> 5) & 1) * 8;
    float pe[8];
#pragma unroll
    for (int e = 0; e < 8; e++) pe[e] = 0.f;
#pragma unroll
    for (int j = 0; j < EMB / 32; j++) {
        int d = lane + 32 * j;
        float xv = sxm[grp][d];
#pragma unroll
        for (int e = 0; e < 8; e++) pe[e] += xv * swg[(ebase + e) * WGP + d];
    }
#pragma unroll
    for (int e = 0; e < 8; e++) {
#pragma unroll
        for (int o = 16; o > 0; o >>= 1) pe[e] += __shfl_xor_sync(0xffffffffu, pe[e], o);
    }
    if (lane == 0) {
#pragma unroll
        for (int e = 0; e < 8; e++) glog[grp][ebase + e] = pe[e];
    }
    __syncthreads();

    if (t == 0) {
        float z[NE];
#pragma unroll
        for (int e = 0; e < NE; e++) z[e] = glog[grp][e];
        float zm = z[0]; int idx = 0;
#pragma unroll
        for (int e = 1; e < NE; e++) {
            if (z[e] > zm) { zm = z[e]; idx = e; }
        }
        float s = 0.f;
#pragma unroll
        for (int e = 0; e < NE; e++) s += expf(z[e] - zm);
        g_eidx[b]  = idx;
        g_gatev[b] = 1.f / s;
        g_logits[2 * b]     = 0.f;
        g_logits[2 * b + 1] = 0.f;
    }
}

// -------------------- 3) parallel capacity routing ----------------------------
__global__ __launch_bounds__(512) void k_route1() {
    __shared__ int wcnt[16][NE];
    int tid = threadIdx.x, c = blockIdx.x;
    int warp = tid >> 5, lane = tid & 31;

    for (int i = tid; i < NE * CAP / 16; i += 512) g_elist[c * (NE * CAP / 16) + i] = -1;
    if (tid < 16 * NE) ((int*)wcnt)[tid] = 0;
    __syncthreads();

    int b = c * 512 + tid;
    int e = g_eidx[b];
    unsigned m = __match_any_sync(0xffffffffu, e);
    int rank = __popc(m & ((1u << lane) - 1u));
    if (rank == 0) wcnt[warp][e] = __popc(m);
    __syncthreads();

    if (tid < NE) {
        int run = 0;
#pragma unroll
        for (int w = 0; w < 16; w++) {
            int v = wcnt[w][tid];
            wcnt[w][tid] = run;
            run += v;
        }
        g_ccnt[c * NE + tid] = run;
    }
    __syncthreads();
    g_pos[b] = wcnt[warp][e] + rank;
}

// scatter; per-block redundant scan of chunk bases
__global__ __launch_bounds__(512) void k_route3() {
    __shared__ int sbase[NE];
    int tid = threadIdx.x, c = blockIdx.x;
    if (tid < NE) {
        int run = 0;
        for (int cc = 0; cc < 16; cc++) {
            int v = g_ccnt[cc * NE + tid];
            if (cc == c) { sbase[tid] = run; }
            run += v;
        }
    }
    __syncthreads();
    int b = c * 512 + tid;
    int e = g_eidx[b];
    int pos = sbase[e] + g_pos[b];
    if (pos < CAP) g_elist[e * CAP + pos] = b;
}

// -- GEMM config (3-stage A cp.async 2-ahead, 2-deep B register pipeline) -----
#define APITCH 40    // 32 + 8 bf16 pad
#define BPITCH 136   // 128 + 8 bf16 pad
#define ACH    (128 * APITCH * 2)          // 10240 B per A stage
#define BCH    (32 * BPITCH * 2)           // 8704 B per B stage
#define GHDR   2048                        // [0..512) sTok, [512..1536) sFc
#define SAOF   GHDR
#define SBOF   (GHDR + 3 * ACH)
#define GSMEM  (SBOF + 2 * BCH)            // 50176 B (opt-in)

// -------------------- 4) FFN GEMM1: h = relu(xe @ w1 + b1) -------------------
__global__ __launch_bounds__(256) void k_ffn1(const float* __restrict__ w1,
                                              const float* __restrict__ b1) {
    extern __shared__ __align__(1024) char smem[];
    uint32_t sb = su32(smem);
    int* sTok = (int*)smem;

    int e  = blockIdx.z;
    int m0 = blockIdx.x * 128;
    int n0 = blockIdx.y * 128;
    int tid = threadIdx.x;

    if (tid < 128) sTok[tid] = g_elist[e * CAP + m0 + tid];
    __syncthreads();

    int ra0 = tid >> 2;
    int ka  = (tid & 3) * 8;
    int ra1 = ra0 + 64;
    int tok0 = sTok[ra0], tok1 = sTok[ra1];
    const __nv_bfloat16* A0 = g_xm_bf + (size_t)(tok0 < 0 ? 0 : tok0) * EMB + ka;
    const __nv_bfloat16* A1 = g_xm_bf + (size_t)(tok1 < 0 ? 0 : tok1) * EMB + ka;
    int rb0 = tid >> 4;
    int nb  = (tid & 15) * 8;
    const float* Bp = w1 + (size_t)e * EMB * FFN + (size_t)rb0 * FFN + n0 + nb;

    unsigned aOff0 = (unsigned)((ra0 * APITCH + ka) * 2);
    unsigned aOff1 = (unsigned)((ra1 * APITCH + ka) * 2);
    unsigned bOff0 = (unsigned)((rb0 * BPITCH + nb) * 2);
    unsigned bOff1 = (unsigned)(((rb0 + 16) * BPITCH + nb) * 2);

    auto ldBto = [&](int c, float (&d)[16]) {
        const float* p = Bp + (size_t)(c * 32) * FFN;
        float4 x0 = *reinterpret_cast<const float4*>(p);
        float4 x1 = *reinterpret_cast<const float4*>(p + 4);
        float4 x2 = *reinterpret_cast<const float4*>(p + (size_t)16 * FFN);
        float4 x3 = *reinterpret_cast<const float4*>(p + (size_t)16 * FFN + 4);
        d[0]=x0.x; d[1]=x0.y; d[2]=x0.z; d[3]=x0.w;
        d[4]=x1.x; d[5]=x1.y; d[6]=x1.z; d[7]=x1.w;
        d[8]=x2.x; d[9]=x2.y; d[10]=x2.z; d[11]=x2.w;
        d[12]=x3.x; d[13]=x3.y; d[14]=x3.z; d[15]=x3.w;
    };
    auto stsBfrom = [&](const float (&d)[16], int s) {
        __nv_bfloat162 h0[4], h1[4];
#pragma unroll
        for (int q = 0; q < 4; q++) {
            h0[q] = __floats2bfloat162_rn(d[2 * q],     d[2 * q + 1]);
            h1[q] = __floats2bfloat162_rn(d[8 + 2 * q], d[8 + 2 * q + 1]);
        }
        char* base = smem + SBOF + s * BCH;
        *reinterpret_cast<uint4*>(base + bOff0) = *reinterpret_cast<uint4*>(h0);
        *reinterpret_cast<uint4*>(base + bOff1) = *reinterpret_cast<uint4*>(h1);
    };
    auto issueA = [&](int c, int st) {
        int k0 = c * 32;
        unsigned base = sb + SAOF + st * ACH;
        cp16(base + aOff0, A0 + k0, tok0 >= 0);
        cp16(base + aOff1, A1 + k0, tok1 >= 0);
        CP_COMMIT;
    };

    float brg0[16], brg1[16];
    ldBto(0, brg0); ldBto(1, brg1);
    issueA(0, 0); issueA(1, 1);

    int warp = tid >> 5;
    int wm = warp & 3, wn = warp >> 2;
    int lane = tid & 31;
    int g = lane >> 2, tq = lane & 3;
    int aRow = wm * 32 + (lane & 7) + ((lane >> 3) & 1) * 8;
    int aCol = (lane >> 4) * 8;
    int bRow = (lane & 7) + ((lane >> 3) & 1) * 8;
    int bCol = wn * 64 + (lane >> 4) * 8;

    float acc[2][8][4];
#pragma unroll
    for (int mi = 0; mi < 2; mi++)
#pragma unroll
        for (int ni = 0; ni < 8; ni++)
#pragma unroll
            for (int q = 0; q < 4; q++) acc[mi][ni][q] = 0.f;

    const int NK = EMB / 32;   // 16
    auto body = [&](int ki, float (&bc)[16]) {
        int sA = ki % 3;
        stsBfrom(bc, ki & 1);
        if (ki + 2 < NK) {
            ldBto(ki + 2, bc);
            issueA(ki + 2, (ki + 2) % 3);
            CP_WAIT(2);
        } else if (ki + 1 < NK) { CP_WAIT(1); }
        else { CP_WAIT(0); }
        __syncthreads();
        unsigned aB = sb + SAOF + sA * ACH;
        unsigned bB = sb + SBOF + (ki & 1) * BCH;
#pragma unroll
        for (int ks = 0; ks < 2; ks++) {
            unsigned a[2][4];
            ldsm4(aB + (unsigned)((aRow * APITCH + ks * 16 + aCol) * 2),
                  a[0][0], a[0][1], a[0][2], a[0][3]);
            ldsm4(aB + (unsigned)(((aRow + 16) * APITCH + ks * 16 + aCol) * 2),
                  a[1][0], a[1][1], a[1][2], a[1][3]);
            unsigned bf[8][2];
#pragma unroll
            for (int p = 0; p < 4; p++) {
                unsigned r0, r1, r2, r3;
                ldsm4t(bB + (unsigned)(((ks * 16 + bRow) * BPITCH + bCol + p * 16) * 2),
                       r0, r1, r2, r3);
                bf[2 * p][0] = r0; bf[2 * p][1] = r1;
                bf[2 * p + 1][0] = r2; bf[2 * p + 1][1] = r3;
            }
#pragma unroll
            for (int mi = 0; mi < 2; mi++)
#pragma unroll
                for (int ni = 0; ni < 8; ni++) mma16816(acc[mi][ni], a[mi], bf[ni]);
        }
        __syncthreads();
    };

#pragma unroll 1
    for (int kk = 0; kk < NK; kk += 2) {
        body(kk, brg0);
        body(kk + 1, brg1);
    }

    const float* b1e = b1 + e * FFN;
#pragma unroll
    for (int mi = 0; mi < 2; mi++) {
        int r0 = wm * 32 + mi * 16 + g;
#pragma unroll
        for (int ni = 0; ni < 8; ni++) {
            int nl = wn * 64 + ni * 8 + tq * 2;
            int n = n0 + nl;
            float bb0 = b1e[n], bb1 = b1e[n + 1];
            float h00 = fmaxf(acc[mi][ni][0] + bb0, 0.f);
            float h01 = fmaxf(acc[mi][ni][1] + bb1, 0.f);
            float h10 = fmaxf(acc[mi][ni][2] + bb0, 0.f);
            float h11 = fmaxf(acc[mi][ni][3] + bb1, 0.f);
            __nv_bfloat162* o0 = reinterpret_cast<__nv_bfloat162*>(
                g_h + (size_t)(e * CAP + m0 + r0) * FFN + n);
            __nv_bfloat162* o1 = reinterpret_cast<__nv_bfloat162*>(
                g_h + (size_t)(e * CAP + m0 + r0 + 8) * FFN + n);
            *o0 = __floats2bfloat162_rn(h00, h01);
            *o1 = __floats2bfloat162_rn(h10, h11);
        }
    }
}

// ---- 5) FFN GEMM2 (split-K): ye = h @ w2 + b2, fused classifier + scatter ---
__global__ __launch_bounds__(256) void k_ffn2(const float* __restrict__ w2,
                                              const float* __restrict__ b2,
                                              const float* __restrict__ fcw) {
    extern __shared__ __align__(1024) char smem[];
    uint32_t sb = su32(smem);
    int*   sTok = (int*)smem;
    float* sFc  = (float*)(smem + 512);

    int e  = blockIdx.z;
    int kz = blockIdx.x >> 2;           // K-split half (0/1)
    int m0 = (blockIdx.x & 3) * 128;
    int n0 = blockIdx.y * 128;
    int kbase = kz * (FFN / 2);
    int tid = threadIdx.x;

    if (tid < 128) {
        sTok[tid] = g_elist[e * CAP + m0 + tid];
        sFc[2 * tid]     = fcw[(n0 + tid) * 2];
        sFc[2 * tid + 1] = fcw[(n0 + tid) * 2 + 1];
    }
    __syncthreads();

    int ra0 = tid >> 2;
    int ka  = (tid & 3) * 8;
    int ra1 = ra0 + 64;
    const __nv_bfloat16* Ab = g_h + (size_t)(e * CAP + m0) * FFN + kbase + ka;
    int rb0 = tid >> 4;
    int nb  = (tid & 15) * 8;
    const float* Bp = w2 + (size_t)e * FFN * EMB + (size_t)(kbase + rb0) * EMB + n0 + nb;

    unsigned aOff0 = (unsigned)((ra0 * APITCH + ka) * 2);
    unsigned aOff1 = (unsigned)((ra1 * APITCH + ka) * 2);
    unsigned bOff0 = (unsigned)((rb0 * BPITCH + nb) * 2);
    unsigned bOff1 = (unsigned)(((rb0 + 16) * BPITCH + nb) * 2);

    auto ldBto = [&](int c, float (&d)[16]) {
        const float* p = Bp + (size_t)(c * 32) * EMB;
        float4 x0 = *reinterpret_cast<const float4*>(p);
        float4 x1 = *reinterpret_cast<const float4*>(p + 4);
        float4 x2 = *reinterpret_cast<const float4*>(p + (size_t)16 * EMB);
        float4 x3 = *reinterpret_cast<const float4*>(p + (size_t)16 * EMB + 4);
        d[0]=x0.x; d[1]=x0.y; d[2]=x0.z; d[3]=x0.w;
        d[4]=x1.x; d[5]=x1.y; d[6]=x1.z; d[7]=x1.w;
        d[8]=x2.x; d[9]=x2.y; d[10]=x2.z; d[11]=x2.w;
        d[12]=x3.x; d[13]=x3.y; d[14]=x3.z; d[15]=x3.w;
    };
    auto stsBfrom = [&](const float (&d)[16], int s) {
        __nv_bfloat162 h0[4], h1[4];
#pragma unroll
        for (int q = 0; q < 4; q++) {
            h0[q] = __floats2bfloat162_rn(d[2 * q],     d[2 * q + 1]);
            h1[q] = __floats2bfloat162_rn(d[8 + 2 * q], d[8 + 2 * q + 1]);
        }
        char* base = smem + SBOF + s * BCH;
        *reinterpret_cast<uint4*>(base + bOff0) = *reinterpret_cast<uint4*>(h0);
        *reinterpret_cast<uint4*>(base + bOff1) = *reinterpret_cast<uint4*>(h1);
    };
    auto issueA = [&](int c, int st) {
        int k0 = c * 32;
        unsigned base = sb + SAOF + st * ACH;
        cp16(base + aOff0, Ab + (size_t)ra0 * FFN + k0, true);
        cp16(base + aOff1, Ab + (size_t)ra1 * FFN + k0, true);
        CP_COMMIT;
    };

    float brg0[16], brg1[16];
    ldBto(0, brg0); ldBto(1, brg1);
    issueA(0, 0); issueA(1, 1);

    int warp = tid >> 5;
    int wm = warp & 3, wn = warp >> 2;
    int lane = tid & 31;
    int g = lane >> 2, tq = lane & 3;
    int aRow = wm * 32 + (lane & 7) + ((lane >> 3) & 1) * 8;
    int aCol = (lane >> 4) * 8;
    int bRow = (lane & 7) + ((lane >> 3) & 1) * 8;
    int bCol = wn * 64 + (lane >> 4) * 8;

    float acc[2][8][4];
#pragma unroll
    for (int mi = 0; mi < 2; mi++)
#pragma unroll
        for (int ni = 0; ni < 8; ni++)
#pragma unroll
            for (int q = 0; q < 4; q++) acc[mi][ni][q] = 0.f;

    const int NK = (FFN / 2) / 32;   // 32
    auto body = [&](int ki, float (&bc)[16]) {
        int sA = ki % 3;
        stsBfrom(bc, ki & 1);
        if (ki + 2 < NK) {
            ldBto(ki + 2, bc);
            issueA(ki + 2, (ki + 2) % 3);
            CP_WAIT(2);
        } else if (ki + 1 < NK) { CP_WAIT(1); }
        else { CP_WAIT(0); }
        __syncthreads();
        unsigned aB = sb + SAOF + sA * ACH;
        unsigned bB = sb + SBOF + (ki & 1) * BCH;
#pragma unroll
        for (int ks = 0; ks < 2; ks++) {
            unsigned a[2][4];
            ldsm4(aB + (unsigned)((aRow * APITCH + ks * 16 + aCol) * 2),
                  a[0][0], a[0][1], a[0][2], a[0][3]);
            ldsm4(aB + (unsigned)(((aRow + 16) * APITCH + ks * 16 + aCol) * 2),
                  a[1][0], a[1][1], a[1][2], a[1][3]);
            unsigned bf[8][2];
#pragma unroll
            for (int p = 0; p < 4; p++) {
                unsigned r0, r1, r2, r3;
                ldsm4t(bB + (unsigned)(((ks * 16 + bRow) * BPITCH + bCol + p * 16) * 2),
                       r0, r1, r2, r3);
                bf[2 * p][0] = r0; bf[2 * p][1] = r1;
                bf[2 * p + 1][0] = r2; bf[2 * p + 1][1] = r3;
            }
#pragma unroll
            for (int mi = 0; mi < 2; mi++)
#pragma unroll
                for (int ni = 0; ni < 8; ni++) mma16816(acc[mi][ni], a[mi], bf[ni]);
        }
        __syncthreads();
    };

#pragma unroll 1
    for (int kk = 0; kk < NK; kk += 2) {
        body(kk, brg0);
        body(kk + 1, brg1);
    }

    // epilogue: contract (acc + b2?) against fc_w columns, gate-scale, scatter
    float p[2][2][2];
#pragma unroll
    for (int mi = 0; mi < 2; mi++)
#pragma unroll
        for (int h = 0; h < 2; h++) { p[mi][h][0] = 0.f; p[mi][h][1] = 0.f; }

    const float* b2e = b2 + e * EMB;
    float bscale = (kz == 0) ? 1.f : 0.f;   // bias added by kz=0 half only
#pragma unroll
    for (int mi = 0; mi < 2; mi++) {
#pragma unroll
        for (int ni = 0; ni < 8; ni++) {
            int nl = wn * 64 + ni * 8 + tq * 2;
            float w00 = sFc[2 * nl],     w01 = sFc[2 * nl + 1];
            float w10 = sFc[2 * nl + 2], w11 = sFc[2 * nl + 3];
            float bb0 = bscale * b2e[n0 + nl], bb1 = bscale * b2e[n0 + nl + 1];
            float v0 = acc[mi][ni][0] + bb0, v1 = acc[mi][ni][1] + bb1;
            float v2 = acc[mi][ni][2] + bb0, v3 = acc[mi][ni][3] + bb1;
            p[mi][0][0] += v0 * w00 + v1 * w10;
            p[mi][0][1] += v0 * w01 + v1 * w11;
            p[mi][1][0] += v2 * w00 + v3 * w10;
            p[mi][1][1] += v2 * w01 + v3 * w11;
        }
    }
#pragma unroll
    for (int mi = 0; mi < 2; mi++) {
#pragma unroll
        for (int h = 0; h < 2; h++) {
            int row = wm * 32 + mi * 16 + g + h * 8;
            int tok = sTok[row];
            if (tok >= 0) {
                float gv = g_gatev[tok];
                atomicAdd(&g_logits[2 * tok],     gv * p[mi][h][0]);
                atomicAdd(&g_logits[2 * tok + 1], gv * p[mi][h][1]);
            }
        }
    }
}

// -------------------- 6) final log_softmax -----------------------------------
__global__ void k_out(const float* __restrict__ fcb, float* __restrict__ out) {
    int b = blockIdx.x * blockDim.x + threadIdx.x;
    if (b < B_TOK) {
        float z0 = g_logits[2 * b] + fcb[0];
        float z1 = g_logits[2 * b + 1] + fcb[1];
        float m = fmaxf(z0, z1);
        float l = m + logf(expf(z0 - m) + expf(z1 - m));
        out[2 * b]     = z0 - l;
        out[2 * b + 1] = z1 - l;
    }
}

// ------------------------------- launcher ------------------------------------
extern "C" void kernel_launch(void* const* d_in, const int* in_sizes, int n_in,
                              void* d_out, int out_size) {
    (void)in_sizes; (void)n_in; (void)out_size;
    const int*   x   = (const int*)d_in[0];
    const float* emb = (const float*)d_in[1];
    const float* wg  = (const float*)d_in[2];
    const float* w1  = (const float*)d_in[3];
    const float* b1  = (const float*)d_in[4];
    const float* w2  = (const float*)d_in[5];
    const float* b2  = (const float*)d_in[6];
    const float* fcw = (const float*)d_in[7];
    const float* fcb = (const float*)d_in[8];
    float* out = (float*)d_out;

    static bool s_init = false;
    if (!s_init) {
        s_init = true;
        cudaFuncSetAttribute(k_ffn1, cudaFuncAttributeMaxDynamicSharedMemorySize, GSMEM);
        cudaFuncSetAttribute(k_ffn2, cudaFuncAttributeMaxDynamicSharedMemorySize, GSMEM);
    }

    k_cvt_emb<<<(VOCAB * EMB / 8) / 256, 256>>>((const float4*)emb);
    k_pool_gate<<<B_TOK / 4, 256>>>(x, wg);
    k_route1<<<16, 512>>>();
    k_route3<<<16, 512>>>();
    k_ffn1<<<dim3(CAP / 128, FFN / 128, NE), 256, GSMEM>>>(w1, b1);
    k_ffn2<<<dim3(8, EMB / 128, NE), 256, GSMEM>>>(w2, b2, fcw);
    k_out<<<B_TOK / 256, 256>>>(fcb, out);
}

// round 12
// speedup vs baseline: 1.1988x; 1.0922x over previous
#include <cuda_runtime.h>
#include <cuda_bf16.h>
#include <math.h>
#include <stdint.h>

#define B_TOK 8192
#define SEQ   64
#define EMB   512
#define NE    16
#define FFN   2048
#define CAP   512
#define NOUT  2
#define VOCAB 50000

// ------------------------- scratch (static device memory) -------------------
__device__ __nv_bfloat16  g_xm_bf[B_TOK * EMB];       // bf16 pooled embeddings (GEMM A)
__device__ __nv_bfloat16  g_embb[VOCAB * EMB];        // bf16 embedding table
__device__ float          g_gatev[B_TOK];             // gate prob of chosen expert
__device__ int            g_eidx[B_TOK];              // chosen expert per token
__device__ int            g_pos[B_TOK];               // slot within (chunk, expert)
__device__ int            g_ccnt[16 * NE];            // per-chunk expert counts
__device__ int            g_elist[NE * CAP];          // token id per (expert, slot), -1 empty
__device__ __nv_bfloat16  g_h[NE * CAP * FFN];        // hidden activations (post-relu)
__device__ float          g_logits[B_TOK * NOUT];     // pre-log-softmax logits (no fc_b)

// ------------------------------- helpers ------------------------------------
__device__ __forceinline__ unsigned su32(const void* p) {
    return (unsigned)__cvta_generic_to_shared(p);
}
__device__ __forceinline__ void ldsm4(unsigned addr, unsigned& r0, unsigned& r1,
                                      unsigned& r2, unsigned& r3) {
    asm volatile("ldmatrix.sync.aligned.m8n8.x4.shared.b16 {%0,%1,%2,%3}, [%4];"
                 : "=r"(r0), "=r"(r1), "=r"(r2), "=r"(r3) : "r"(addr));
}
__device__ __forceinline__ void ldsm4t(unsigned addr, unsigned& r0, unsigned& r1,
                                       unsigned& r2, unsigned& r3) {
    asm volatile("ldmatrix.sync.aligned.m8n8.x4.trans.shared.b16 {%0,%1,%2,%3}, [%4];"
                 : "=r"(r0), "=r"(r1), "=r"(r2), "=r"(r3) : "r"(addr));
}
__device__ __forceinline__ void mma16816(float* c, const unsigned* a, const unsigned* b) {
    asm volatile(
        "mma.sync.aligned.m16n8k16.row.col.f32.bf16.bf16.f32 "
        "{%0,%1,%2,%3}, {%4,%5,%6,%7}, {%8,%9}, {%0,%1,%2,%3};"
        : "+f"(c[0]), "+f"(c[1]), "+f"(c[2]), "+f"(c[3])
        : "r"(a[0]), "r"(a[1]), "r"(a[2]), "r"(a[3]), "r"(b[0]), "r"(b[1]));
}
__device__ __forceinline__ void cp16(unsigned dst, const void* src, bool pred) {
    int sz = pred ? 16 : 0;
    asm volatile("cp.async.cg.shared.global [%0], [%1], 16, %2;"
                 :: "r"(dst), "l"(src), "r"(sz));
}
#define CP_COMMIT asm volatile("cp.async.commit_group;")
#define CP_WAIT(n) asm volatile("cp.async.wait_group %0;" :: "n"(n))

// -------------------- 1) embedding fp32 -> bf16 convert ----------------------
__global__ __launch_bounds__(256) void k_cvt_emb(const float4* __restrict__ emb) {
    int i = blockIdx.x * 256 + threadIdx.x;   // VOCAB*EMB/8 threads
    float4 a = emb[2 * i];
    float4 b = emb[2 * i + 1];
    __nv_bfloat162* o = reinterpret_cast<__nv_bfloat162*>(g_embb);
    o[4 * i + 0] = __floats2bfloat162_rn(a.x, a.y);
    o[4 * i + 1] = __floats2bfloat162_rn(a.z, a.w);
    o[4 * i + 2] = __floats2bfloat162_rn(b.x, b.y);
    o[4 * i + 3] = __floats2bfloat162_rn(b.z, b.w);
}

// ---------- 2) fused: embedding gather + mean pool + gate (4 tokens/block) ----
#define WGP 520   // padded wg row pitch (floats)
__global__ __launch_bounds__(256) void k_pool_gate(const int* __restrict__ x,
                                                   const float* __restrict__ wg) {
    __shared__ float swg[NE * WGP];
    __shared__ float sxm[4][EMB];
    __shared__ int   toks[4][SEQ];
    __shared__ float glog[4][NE];

    int tid = threadIdx.x;
    for (int i = tid; i < EMB * NE; i += 256) {
        swg[(i & 15) * WGP + (i >> 4)] = wg[i];
    }
    toks[tid >> 6][tid & 63] = x[blockIdx.x * 256 + tid];
    __syncthreads();

    int grp = tid >> 6;
    int t   = tid & 63;
    int b   = blockIdx.x * 4 + grp;

    float acc[8];
#pragma unroll
    for (int j = 0; j < 8; j++) acc[j] = 0.f;

    const uint4* E = reinterpret_cast<const uint4*>(g_embb);
#pragma unroll
    for (int s = 0; s < SEQ; s += 8) {
        uint4 v[8];
#pragma unroll
        for (int j = 0; j < 8; j++) {
            int ii = toks[grp][s + j] * (EMB / 8) + t;   // 32-bit index math
            v[j] = E[ii];
        }
#pragma unroll
        for (int j = 0; j < 4; j++) {
            const __nv_bfloat162* p0 = reinterpret_cast<const __nv_bfloat162*>(&v[0]);
            const __nv_bfloat162* p1 = reinterpret_cast<const __nv_bfloat162*>(&v[1]);
            const __nv_bfloat162* p2 = reinterpret_cast<const __nv_bfloat162*>(&v[2]);
            const __nv_bfloat162* p3 = reinterpret_cast<const __nv_bfloat162*>(&v[3]);
            const __nv_bfloat162* p4 = reinterpret_cast<const __nv_bfloat162*>(&v[4]);
            const __nv_bfloat162* p5 = reinterpret_cast<const __nv_bfloat162*>(&v[5]);
            const __nv_bfloat162* p6 = reinterpret_cast<const __nv_bfloat162*>(&v[6]);
            const __nv_bfloat162* p7 = reinterpret_cast<const __nv_bfloat162*>(&v[7]);
            __nv_bfloat162 a01 = __hadd2(p0[j], p1[j]);
            __nv_bfloat162 a23 = __hadd2(p2[j], p3[j]);
            __nv_bfloat162 a45 = __hadd2(p4[j], p5[j]);
            __nv_bfloat162 a67 = __hadd2(p6[j], p7[j]);
            __nv_bfloat162 q0  = __hadd2(a01, a23);
            __nv_bfloat162 q1  = __hadd2(a45, a67);
            __nv_bfloat162 q   = __hadd2(q0, q1);
            float2 f = __bfloat1622float2(q);
            acc[2 * j]     += f.x;
            acc[2 * j + 1] += f.y;
        }
    }
    const float inv = 1.0f / (float)SEQ;
#pragma unroll
    for (int j = 0; j < 8; j++) acc[j] *= inv;

    __nv_bfloat162 ob[4];
#pragma unroll
    for (int j = 0; j < 4; j++) ob[j] = __floats2bfloat162_rn(acc[2 * j], acc[2 * j + 1]);
    reinterpret_cast<uint4*>(g_xm_bf)[(size_t)b * (EMB / 8) + t] = *reinterpret_cast<uint4*>(ob);

    float4* sx = reinterpret_cast<float4*>(&sxm[grp][t * 8]);
    sx[0] = make_float4(acc[0], acc[1], acc[2], acc[3]);
    sx[1] = make_float4(acc[4], acc[5], acc[6], acc[7]);
    __syncthreads();

    int lane = tid & 31;
    int ebase = ((tid >> 5) & 1) * 8;
    float pe[8];
#pragma unroll
    for (int e = 0; e < 8; e++) pe[e] = 0.f;
#pragma unroll
    for (int j = 0; j < EMB / 32; j++) {
        int d = lane + 32 * j;
        float xv = sxm[grp][d];
#pragma unroll
        for (int e = 0; e < 8; e++) pe[e] += xv * swg[(ebase + e) * WGP + d];
    }
#pragma unroll
    for (int e = 0; e < 8; e++) {
#pragma unroll
        for (int o = 16; o > 0; o >>= 1) pe[e] += __shfl_xor_sync(0xffffffffu, pe[e], o);
    }
    if (lane == 0) {
#pragma unroll
        for (int e = 0; e < 8; e++) glog[grp][ebase + e] = pe[e];
    }
    __syncthreads();

    if (t == 0) {
        float z[NE];
#pragma unroll
        for (int e = 0; e < NE; e++) z[e] = glog[grp][e];
        float zm = z[0]; int idx = 0;
#pragma unroll
        for (int e = 1; e < NE; e++) {
            if (z[e] > zm) { zm = z[e]; idx = e; }
        }
        float s = 0.f;
#pragma unroll
        for (int e = 0; e < NE; e++) s += expf(z[e] - zm);
        g_eidx[b]  = idx;
        g_gatev[b] = 1.f / s;
        g_logits[2 * b]     = 0.f;
        g_logits[2 * b + 1] = 0.f;
    }
}

// -------------------- 3) parallel capacity routing ----------------------------
__global__ __launch_bounds__(512) void k_route1() {
    __shared__ int wcnt[16][NE];
    int tid = threadIdx.x, c = blockIdx.x;
    int warp = tid >> 5, lane = tid & 31;

    for (int i = tid; i < NE * CAP / 16; i += 512) g_elist[c * (NE * CAP / 16) + i] = -1;
    if (tid < 16 * NE) ((int*)wcnt)[tid] = 0;
    __syncthreads();

    int b = c * 512 + tid;
    int e = g_eidx[b];
    unsigned m = __match_any_sync(0xffffffffu, e);
    int rank = __popc(m & ((1u << lane) - 1u));
    if (rank == 0) wcnt[warp][e] = __popc(m);
    __syncthreads();

    if (tid < NE) {
        int run = 0;
#pragma unroll
        for (int w = 0; w < 16; w++) {
            int v = wcnt[w][tid];
            wcnt[w][tid] = run;
            run += v;
        }
        g_ccnt[c * NE + tid] = run;
    }
    __syncthreads();
    g_pos[b] = wcnt[warp][e] + rank;
}

// scatter; per-block redundant scan of chunk bases
__global__ __launch_bounds__(512) void k_route3() {
    __shared__ int sbase[NE];
    int tid = threadIdx.x, c = blockIdx.x;
    if (tid < NE) {
        int run = 0;
        for (int cc = 0; cc < 16; cc++) {
            int v = g_ccnt[cc * NE + tid];
            if (cc == c) { sbase[tid] = run; }
            run += v;
        }
    }
    __syncthreads();
    int b = c * 512 + tid;
    int e = g_eidx[b];
    int pos = sbase[e] + g_pos[b];
    if (pos < CAP) g_elist[e * CAP + pos] = b;
}

// -- GEMM config (4-stage A cp.async, 3-stage B smem, ONE sync per k-iter) ----
#define APITCH 40    // 32 + 8 bf16 pad
#define BPITCH 136   // 128 + 8 bf16 pad
#define ACH    (128 * APITCH * 2)          // 10240 B per A stage
#define BCH    (32 * BPITCH * 2)           // 8704 B per B stage
#define GHDR   2048                        // [0..512) sTok, [512..1536) sFc
#define SAOF   GHDR
#define SBOF   (GHDR + 4 * ACH)
#define GSMEM  (SBOF + 3 * BCH)            // 69120 B (opt-in)

// -------------------- 4) FFN GEMM1: h = relu(xe @ w1 + b1) -------------------
__global__ __launch_bounds__(256) void k_ffn1(const float* __restrict__ w1,
                                              const float* __restrict__ b1) {
    extern __shared__ __align__(1024) char smem[];
    uint32_t sb = su32(smem);
    int* sTok = (int*)smem;

    int e  = blockIdx.z;
    int m0 = blockIdx.x * 128;
    int n0 = blockIdx.y * 128;
    int tid = threadIdx.x;

    if (tid < 128) sTok[tid] = g_elist[e * CAP + m0 + tid];
    __syncthreads();

    int ra0 = tid >> 2;
    int ka  = (tid & 3) * 8;
    int ra1 = ra0 + 64;
    int tok0 = sTok[ra0], tok1 = sTok[ra1];
    const __nv_bfloat16* A0 = g_xm_bf + (size_t)(tok0 < 0 ? 0 : tok0) * EMB + ka;
    const __nv_bfloat16* A1 = g_xm_bf + (size_t)(tok1 < 0 ? 0 : tok1) * EMB + ka;
    int rb0 = tid >> 4;
    int nb  = (tid & 15) * 8;
    const float* Bp = w1 + (size_t)e * EMB * FFN + (size_t)rb0 * FFN + n0 + nb;

    unsigned aOff0 = (unsigned)((ra0 * APITCH + ka) * 2);
    unsigned aOff1 = (unsigned)((ra1 * APITCH + ka) * 2);
    unsigned bOff0 = (unsigned)((rb0 * BPITCH + nb) * 2);
    unsigned bOff1 = (unsigned)(((rb0 + 16) * BPITCH + nb) * 2);

    auto ldBto = [&](int c, float (&d)[16]) {
        const float* p = Bp + (size_t)(c * 32) * FFN;
        float4 x0 = *reinterpret_cast<const float4*>(p);
        float4 x1 = *reinterpret_cast<const float4*>(p + 4);
        float4 x2 = *reinterpret_cast<const float4*>(p + (size_t)16 * FFN);
        float4 x3 = *reinterpret_cast<const float4*>(p + (size_t)16 * FFN + 4);
        d[0]=x0.x; d[1]=x0.y; d[2]=x0.z; d[3]=x0.w;
        d[4]=x1.x; d[5]=x1.y; d[6]=x1.z; d[7]=x1.w;
        d[8]=x2.x; d[9]=x2.y; d[10]=x2.z; d[11]=x2.w;
        d[12]=x3.x; d[13]=x3.y; d[14]=x3.z; d[15]=x3.w;
    };
    auto stsBfrom = [&](const float (&d)[16], int s) {
        __nv_bfloat162 h0[4], h1[4];
#pragma unroll
        for (int q = 0; q < 4; q++) {
            h0[q] = __floats2bfloat162_rn(d[2 * q],     d[2 * q + 1]);
            h1[q] = __floats2bfloat162_rn(d[8 + 2 * q], d[8 + 2 * q + 1]);
        }
        char* base = smem + SBOF + s * BCH;
        *reinterpret_cast<uint4*>(base + bOff0) = *reinterpret_cast<uint4*>(h0);
        *reinterpret_cast<uint4*>(base + bOff1) = *reinterpret_cast<uint4*>(h1);
    };
    auto issueA = [&](int c, int st) {
        int k0 = c * 32;
        unsigned base = sb + SAOF + st * ACH;
        cp16(base + aOff0, A0 + k0, tok0 >= 0);
        cp16(base + aOff1, A1 + k0, tok1 >= 0);
        CP_COMMIT;
    };

    float brg0[16], brg1[16];
    ldBto(0, brg0); ldBto(1, brg1);
    issueA(0, 0); issueA(1, 1);

    int warp = tid >> 5;
    int wm = warp & 3, wn = warp >> 2;
    int lane = tid & 31;
    int g = lane >> 2, tq = lane & 3;
    int aRow = wm * 32 + (lane & 7) + ((lane >> 3) & 1) * 8;
    int aCol = (lane >> 4) * 8;
    int bRow = (lane & 7) + ((lane >> 3) & 1) * 8;
    int bCol = wn * 64 + (lane >> 4) * 8;

    float acc[2][8][4];
#pragma unroll
    for (int mi = 0; mi < 2; mi++)
#pragma unroll
        for (int ni = 0; ni < 8; ni++)
#pragma unroll
            for (int q = 0; q < 4; q++) acc[mi][ni][q] = 0.f;

    const int NK = EMB / 32;   // 16
    // single __syncthreads per iteration: write-set {B ki%3, A (ki+2)%4}
    // disjoint from laggard read-set {B (ki-1)%3, A (ki-1)%4}
    auto body = [&](int ki, float (&bc)[16]) {
        int sB = ki % 3;
        stsBfrom(bc, sB);
        if (ki + 2 < NK) {
            ldBto(ki + 2, bc);
            issueA(ki + 2, (ki + 2) & 3);
            CP_WAIT(2);
        } else if (ki + 1 < NK) { CP_WAIT(1); }
        else { CP_WAIT(0); }
        __syncthreads();
        unsigned aB = sb + SAOF + (ki & 3) * ACH;
        unsigned bB = sb + SBOF + sB * BCH;
#pragma unroll
        for (int ks = 0; ks < 2; ks++) {
            unsigned a[2][4];
            ldsm4(aB + (unsigned)((aRow * APITCH + ks * 16 + aCol) * 2),
                  a[0][0], a[0][1], a[0][2], a[0][3]);
            ldsm4(aB + (unsigned)(((aRow + 16) * APITCH + ks * 16 + aCol) * 2),
                  a[1][0], a[1][1], a[1][2], a[1][3]);
            unsigned bf[8][2];
#pragma unroll
            for (int p = 0; p < 4; p++) {
                unsigned r0, r1, r2, r3;
                ldsm4t(bB + (unsigned)(((ks * 16 + bRow) * BPITCH + bCol + p * 16) * 2),
                       r0, r1, r2, r3);
                bf[2 * p][0] = r0; bf[2 * p][1] = r1;
                bf[2 * p + 1][0] = r2; bf[2 * p + 1][1] = r3;
            }
#pragma unroll
            for (int mi = 0; mi < 2; mi++)
#pragma unroll
                for (int ni = 0; ni < 8; ni++) mma16816(acc[mi][ni], a[mi], bf[ni]);
        }
    };

#pragma unroll 1
    for (int kk = 0; kk < NK; kk += 2) {
        body(kk, brg0);
        body(kk + 1, brg1);
    }

    const float* b1e = b1 + e * FFN;
#pragma unroll
    for (int mi = 0; mi < 2; mi++) {
        int r0 = wm * 32 + mi * 16 + g;
#pragma unroll
        for (int ni = 0; ni < 8; ni++) {
            int nl = wn * 64 + ni * 8 + tq * 2;
            int n = n0 + nl;
            float bb0 = b1e[n], bb1 = b1e[n + 1];
            float h00 = fmaxf(acc[mi][ni][0] + bb0, 0.f);
            float h01 = fmaxf(acc[mi][ni][1] + bb1, 0.f);
            float h10 = fmaxf(acc[mi][ni][2] + bb0, 0.f);
            float h11 = fmaxf(acc[mi][ni][3] + bb1, 0.f);
            __nv_bfloat162* o0 = reinterpret_cast<__nv_bfloat162*>(
                g_h + (size_t)(e * CAP + m0 + r0) * FFN + n);
            __nv_bfloat162* o1 = reinterpret_cast<__nv_bfloat162*>(
                g_h + (size_t)(e * CAP + m0 + r0 + 8) * FFN + n);
            *o0 = __floats2bfloat162_rn(h00, h01);
            *o1 = __floats2bfloat162_rn(h10, h11);
        }
    }
}

// ---- 5) FFN GEMM2 (split-K): ye = h @ w2 + b2, fused classifier + scatter ---
__global__ __launch_bounds__(256) void k_ffn2(const float* __restrict__ w2,
                                              const float* __restrict__ b2,
                                              const float* __restrict__ fcw) {
    extern __shared__ __align__(1024) char smem[];
    uint32_t sb = su32(smem);
    int*   sTok = (int*)smem;
    float* sFc  = (float*)(smem + 512);

    int e  = blockIdx.z;
    int kz = blockIdx.x >> 2;           // K-split half (0/1)
    int m0 = (blockIdx.x & 3) * 128;
    int n0 = blockIdx.y * 128;
    int kbase = kz * (FFN / 2);
    int tid = threadIdx.x;

    if (tid < 128) {
        sTok[tid] = g_elist[e * CAP + m0 + tid];
        sFc[2 * tid]     = fcw[(n0 + tid) * 2];
        sFc[2 * tid + 1] = fcw[(n0 + tid) * 2 + 1];
    }
    __syncthreads();

    int ra0 = tid >> 2;
    int ka  = (tid & 3) * 8;
    int ra1 = ra0 + 64;
    const __nv_bfloat16* Ab = g_h + (size_t)(e * CAP + m0) * FFN + kbase + ka;
    int rb0 = tid >> 4;
    int nb  = (tid & 15) * 8;
    const float* Bp = w2 + (size_t)e * FFN * EMB + (size_t)(kbase + rb0) * EMB + n0 + nb;

    unsigned aOff0 = (unsigned)((ra0 * APITCH + ka) * 2);
    unsigned aOff1 = (unsigned)((ra1 * APITCH + ka) * 2);
    unsigned bOff0 = (unsigned)((rb0 * BPITCH + nb) * 2);
    unsigned bOff1 = (unsigned)(((rb0 + 16) * BPITCH + nb) * 2);

    auto ldBto = [&](int c, float (&d)[16]) {
        const float* p = Bp + (size_t)(c * 32) * EMB;
        float4 x0 = *reinterpret_cast<const float4*>(p);
        float4 x1 = *reinterpret_cast<const float4*>(p + 4);
        float4 x2 = *reinterpret_cast<const float4*>(p + (size_t)16 * EMB);
        float4 x3 = *reinterpret_cast<const float4*>(p + (size_t)16 * EMB + 4);
        d[0]=x0.x; d[1]=x0.y; d[2]=x0.z; d[3]=x0.w;
        d[4]=x1.x; d[5]=x1.y; d[6]=x1.z; d[7]=x1.w;
        d[8]=x2.x; d[9]=x2.y; d[10]=x2.z; d[11]=x2.w;
        d[12]=x3.x; d[13]=x3.y; d[14]=x3.z; d[15]=x3.w;
    };
    auto stsBfrom = [&](const float (&d)[16], int s) {
        __nv_bfloat162 h0[4], h1[4];
#pragma unroll
        for (int q = 0; q < 4; q++) {
            h0[q] = __floats2bfloat162_rn(d[2 * q],     d[2 * q + 1]);
            h1[q] = __floats2bfloat162_rn(d[8 + 2 * q], d[8 + 2 * q + 1]);
        }
        char* base = smem + SBOF + s * BCH;
        *reinterpret_cast<uint4*>(base + bOff0) = *reinterpret_cast<uint4*>(h0);
        *reinterpret_cast<uint4*>(base + bOff1) = *reinterpret_cast<uint4*>(h1);
    };
    auto issueA = [&](int c, int st) {
        int k0 = c * 32;
        unsigned base = sb + SAOF + st * ACH;
        cp16(base + aOff0, Ab + (size_t)ra0 * FFN + k0, true);
        cp16(base + aOff1, Ab + (size_t)ra1 * FFN + k0, true);
        CP_COMMIT;
    };

    float brg0[16], brg1[16];
    ldBto(0, brg0); ldBto(1, brg1);
    issueA(0, 0); issueA(1, 1);

    int warp = tid >> 5;
    int wm = warp & 3, wn = warp >> 2;
    int lane = tid & 31;
    int g = lane >> 2, tq = lane & 3;
    int aRow = wm * 32 + (lane & 7) + ((lane >> 3) & 1) * 8;
    int aCol = (lane >> 4) * 8;
    int bRow = (lane & 7) + ((lane >> 3) & 1) * 8;
    int bCol = wn * 64 + (lane >> 4) * 8;

    float acc[2][8][4];
#pragma unroll
    for (int mi = 0; mi < 2; mi++)
#pragma unroll
        for (int ni = 0; ni < 8; ni++)
#pragma unroll
            for (int q = 0; q < 4; q++) acc[mi][ni][q] = 0.f;

    const int NK = (FFN / 2) / 32;   // 32
    auto body = [&](int ki, float (&bc)[16]) {
        int sB = ki % 3;
        stsBfrom(bc, sB);
        if (ki + 2 < NK) {
            ldBto(ki + 2, bc);
            issueA(ki + 2, (ki + 2) & 3);
            CP_WAIT(2);
        } else if (ki + 1 < NK) { CP_WAIT(1); }
        else { CP_WAIT(0); }
        __syncthreads();
        unsigned aB = sb + SAOF + (ki & 3) * ACH;
        unsigned bB = sb + SBOF + sB * BCH;
#pragma unroll
        for (int ks = 0; ks < 2; ks++) {
            unsigned a[2][4];
            ldsm4(aB + (unsigned)((aRow * APITCH + ks * 16 + aCol) * 2),
                  a[0][0], a[0][1], a[0][2], a[0][3]);
            ldsm4(aB + (unsigned)(((aRow + 16) * APITCH + ks * 16 + aCol) * 2),
                  a[1][0], a[1][1], a[1][2], a[1][3]);
            unsigned bf[8][2];
#pragma unroll
            for (int p = 0; p < 4; p++) {
                unsigned r0, r1, r2, r3;
                ldsm4t(bB + (unsigned)(((ks * 16 + bRow) * BPITCH + bCol + p * 16) * 2),
                       r0, r1, r2, r3);
                bf[2 * p][0] = r0; bf[2 * p][1] = r1;
                bf[2 * p + 1][0] = r2; bf[2 * p + 1][1] = r3;
            }
#pragma unroll
            for (int mi = 0; mi < 2; mi++)
#pragma unroll
                for (int ni = 0; ni < 8; ni++) mma16816(acc[mi][ni], a[mi], bf[ni]);
        }
    };

#pragma unroll 1
    for (int kk = 0; kk < NK; kk += 2) {
        body(kk, brg0);
        body(kk + 1, brg1);
    }

    // epilogue: contract (acc + b2?) against fc_w columns, gate-scale, scatter
    float p[2][2][2];
#pragma unroll
    for (int mi = 0; mi < 2; mi++)
#pragma unroll
        for (int h = 0; h < 2; h++) { p[mi][h][0] = 0.f; p[mi][h][1] = 0.f; }

    const float* b2e = b2 + e * EMB;
    float bscale = (kz == 0) ? 1.f : 0.f;   // bias added by kz=0 half only
#pragma unroll
    for (int mi = 0; mi < 2; mi++) {
#pragma unroll
        for (int ni = 0; ni < 8; ni++) {
            int nl = wn * 64 + ni * 8 + tq * 2;
            float w00 = sFc[2 * nl],     w01 = sFc[2 * nl + 1];
            float w10 = sFc[2 * nl + 2], w11 = sFc[2 * nl + 3];
            float bb0 = bscale * b2e[n0 + nl], bb1 = bscale * b2e[n0 + nl + 1];
            float v0 = acc[mi][ni][0] + bb0, v1 = acc[mi][ni][1] + bb1;
            float v2 = acc[mi][ni][2] + bb0, v3 = acc[mi][ni][3] + bb1;
            p[mi][0][0] += v0 * w00 + v1 * w10;
            p[mi][0][1] += v0 * w01 + v1 * w11;
            p[mi][1][0] += v2 * w00 + v3 * w10;
            p[mi][1][1] += v2 * w01 + v3 * w11;
        }
    }
#pragma unroll
    for (int mi = 0; mi < 2; mi++) {
#pragma unroll
        for (int h = 0; h < 2; h++) {
            int row = wm * 32 + mi * 16 + g + h * 8;
            int tok = sTok[row];
            if (tok >= 0) {
                float gv = g_gatev[tok];
                atomicAdd(&g_logits[2 * tok],     gv * p[mi][h][0]);
                atomicAdd(&g_logits[2 * tok + 1], gv * p[mi][h][1]);
            }
        }
    }
}

// -------------------- 6) final log_softmax -----------------------------------
__global__ void k_out(const float* __restrict__ fcb, float* __restrict__ out) {
    int b = blockIdx.x * blockDim.x + threadIdx.x;
    if (b < B_TOK) {
        float z0 = g_logits[2 * b] + fcb[0];
        float z1 = g_logits[2 * b + 1] + fcb[1];
        float m = fmaxf(z0, z1);
        float l = m + logf(expf(z0 - m) + expf(z1 - m));
        out[2 * b]     = z0 - l;
        out[2 * b + 1] = z1 - l;
    }
}

// ------------------------------- launcher ------------------------------------
extern "C" void kernel_launch(void* const* d_in, const int* in_sizes, int n_in,
                              void* d_out, int out_size) {
    (void)in_sizes; (void)n_in; (void)out_size;
    const int*   x   = (const int*)d_in[0];
    const float* emb = (const float*)d_in[1];
    const float* wg  = (const float*)d_in[2];
    const float* w1  = (const float*)d_in[3];
    const float* b1  = (const float*)d_in[4];
    const float* w2  = (const float*)d_in[5];
    const float* b2  = (const float*)d_in[6];
    const float* fcw = (const float*)d_in[7];
    const float* fcb = (const float*)d_in[8];
    float* out = (float*)d_out;

    static bool s_init = false;
    if (!s_init) {
        s_init = true;
        cudaFuncSetAttribute(k_ffn1, cudaFuncAttributeMaxDynamicSharedMemorySize, GSMEM);
        cudaFuncSetAttribute(k_ffn2, cudaFuncAttributeMaxDynamicSharedMemorySize, GSMEM);
    }

    k_cvt_emb<<<(VOCAB * EMB / 8) / 256, 256>>>((const float4*)emb);
    k_pool_gate<<<B_TOK / 4, 256>>>(x, wg);
    k_route1<<<16, 512>>>();
    k_route3<<<16, 512>>>();
    k_ffn1<<<dim3(CAP / 128, FFN / 128, NE), 256, GSMEM>>>(w1, b1);
    k_ffn2<<<dim3(8, EMB / 128, NE), 256, GSMEM>>>(w2, b2, fcw);
    k_out<<<B_TOK / 256, 256>>>(fcb, out);
}